// round 7
// baseline (speedup 1.0000x reference)
#include <cuda_runtime.h>
#include <cstdint>

#define NB 32
#define ND 256
#define NT 2048
#define NL 8
#define NK 1024
#define NVEC (NB*NT)
#define NOUT (NB*ND*NT)
#define NIDX (NB*NL*NT)

#define TM 64                        // rows per CTA
#define NTHREADS 256
#define TILEN 128                    // codes per ntile
#define NTILES (NK/TILEN)            // 8
#define CAP 64

// A buffer: bf16 [64][264] (264 = 256 + 8 pad halves; 528B rows, 16B aligned)
#define A_STRIDE_H 264
#define A_BYTES (TM * A_STRIDE_H * 2)        // 33792
// B stage buffer: bf16 [128][40] (40 halves = 80B rows), double buffered
#define B_STRIDE_H 40
#define B_STAGE_BYTES (TILEN * B_STRIDE_H * 2)   // 10240
#define B_OFF   A_BYTES
#define NS_OFF  (B_OFF + 2 * B_STAGE_BYTES)      // 54272
#define AN_OFF  (NS_OFF + NK * 4)                // 58368
#define RM_OFF  (AN_OFF + TM * 4)                // 58624
#define CNT_OFF (RM_OFF + TM * 4)                // 58880
#define RI_OFF  (CNT_OFF + TM * 4)               // 59136
#define CD_OFF  (RI_OFF + TM * 4)                // 59392
#define PBV_OFF (CD_OFF + TM * CAP * 4)          // 75776
#define PBI_OFF (PBV_OFF + TM * 4 * 4)           // 76800
#define SMEM_BYTES (PBI_OFF + TM * 4 * 4)        // 77824

// Scratch (static device allocations are the sanctioned workaround)
__device__ float    g_res[(size_t)NVEC * ND];
__device__ float    g_norms[NL * NK];
__device__ unsigned g_nsmax[NL];                 // per-layer max |W|^2 (float bits)

// ---------------------------------------------------------------- helpers
__device__ __forceinline__ uint32_t bf2(float lo, float hi) {
    uint32_t r; asm("cvt.rn.bf16x2.f32 %0, %1, %2;" : "=r"(r) : "f"(hi), "f"(lo));
    return r;
}
__device__ __forceinline__ void ldsm4(uint32_t* r, uint32_t addr) {
    asm volatile("ldmatrix.sync.aligned.m8n8.x4.shared.b16 {%0,%1,%2,%3}, [%4];"
        : "=r"(r[0]), "=r"(r[1]), "=r"(r[2]), "=r"(r[3]) : "r"(addr));
}
__device__ __forceinline__ void mma_bf16(float* c, const uint32_t* a,
                                         uint32_t b0, uint32_t b1) {
    asm volatile(
        "mma.sync.aligned.m16n8k16.row.col.f32.bf16.bf16.f32 "
        "{%0,%1,%2,%3}, {%4,%5,%6,%7}, {%8,%9}, {%0,%1,%2,%3};"
        : "+f"(c[0]), "+f"(c[1]), "+f"(c[2]), "+f"(c[3])
        : "r"(a[0]), "r"(a[1]), "r"(a[2]), "r"(a[3]), "r"(b0), "r"(b1));
}

// XLA-style warp row-reduce (mul then add, NO fma), xor-butterfly tree.
__device__ __forceinline__ float warp_sumsq_x32(const float* __restrict__ p, int lane) {
    float s = 0.f;
    #pragma unroll
    for (int i = 0; i < ND / 32; i++) {
        float v = p[lane + 32 * i];
        s = __fadd_rn(s, __fmul_rn(v, v));
    }
    #pragma unroll
    for (int o = 16; o; o >>= 1)
        s = __fadd_rn(s, __shfl_xor_sync(0xffffffffu, s, o));
    return s;
}

// ---------------------------------------------------------------- codebook norms
__global__ void norms_kernel(const float* __restrict__ cb) {
    int w    = (blockIdx.x * blockDim.x + threadIdx.x) >> 5;
    int lane = threadIdx.x & 31;
    if (w >= NL * NK) return;
    float s = warp_sumsq_x32(cb + (size_t)w * ND, lane);
    if (lane == 0) {
        g_norms[w] = s;
        atomicMax(&g_nsmax[w >> 10], __float_as_uint(s));   // positive: uint order == float order
    }
}

// ---------------------------------------------------------------- x (B,D,T) -> res (N,D)
__global__ void tin_kernel(const float* __restrict__ x) {
    __shared__ float tile[32][33];
    int b  = blockIdx.z;
    int d0 = blockIdx.y * 32, t0 = blockIdx.x * 32;
    int tx = threadIdx.x, ty = threadIdx.y;
    #pragma unroll
    for (int i = 0; i < 32; i += 8)
        tile[ty + i][tx] = x[((size_t)b * ND + d0 + ty + i) * NT + t0 + tx];
    __syncthreads();
    #pragma unroll
    for (int i = 0; i < 32; i += 8)
        g_res[((size_t)(b * NT + t0 + ty + i)) * ND + d0 + tx] = tile[tx][ty + i];
}

// ---------------------------------------------------------------- out = x - res
__global__ void tout_kernel(const float* __restrict__ x, float* __restrict__ out) {
    __shared__ float tile[32][33];
    int b  = blockIdx.z;
    int d0 = blockIdx.y * 32, t0 = blockIdx.x * 32;
    int tx = threadIdx.x, ty = threadIdx.y;
    #pragma unroll
    for (int i = 0; i < 32; i += 8)
        tile[ty + i][tx] = g_res[((size_t)(b * NT + t0 + ty + i)) * ND + d0 + tx];
    __syncthreads();
    size_t base = (size_t)b * ND * NT;
    #pragma unroll
    for (int i = 0; i < 32; i += 8) {
        size_t o = base + (size_t)(d0 + ty + i) * NT + t0 + tx;
        out[o] = __fsub_rn(x[o], tile[tx][ty + i]);
    }
}

// ---------------------------------------------------------------- one RVQ layer
__global__ void __launch_bounds__(NTHREADS, 2) vq_layer_kernel(
    const float* __restrict__ codebooks,
    float* __restrict__ idx_out,
    int l, int write_idx)
{
    extern __shared__ char smem[];
    uint32_t* Au     = (uint32_t*)smem;               // bf16 A, word-addressed
    float*    Ns     = (float*)(smem + NS_OFF);
    float*    An     = (float*)(smem + AN_OFF);
    uint32_t* runmin = (uint32_t*)(smem + RM_OFF);
    int*      cnt    = (int*)(smem + CNT_OFF);
    int*      RowIdx = (int*)(smem + RI_OFF);
    uint32_t* cand   = (uint32_t*)(smem + CD_OFF);
    float*    pbv    = (float*)(smem + PBV_OFF);
    int*      pbi    = (int*)(smem + PBI_OFF);

    uint32_t sbase;
    asm("{ .reg .u64 t; cvta.to.shared.u64 t, %1; cvt.u32.u64 %0, t; }"
        : "=r"(sbase) : "l"(smem));

    const float* W  = codebooks + (size_t)l * NK * ND;
    const int row0  = blockIdx.x * TM;
    const float* gA = g_res + (size_t)row0 * ND;
    const int tid   = threadIdx.x;
    const int lane  = tid & 31;
    const int warp  = tid >> 5;
    const int mg    = warp & 1;        // M-group (32 rows)
    const int ng    = warp >> 1;       // N-group (32 cols within ntile)
    const int lr    = lane >> 2, lc = lane & 3;
    const float nsM = __uint_as_float(g_nsmax[l]);

    for (int i = tid; i < NK; i += NTHREADS) Ns[i] = g_norms[l * NK + i];
    if (tid < TM) { cnt[tid] = 0; runmin[tid] = 0x7F7FFFFFu; }

    // ---- |r|^2 per row, XLA reduce order ----
    #pragma unroll
    for (int rr = 0; rr < TM / 8; rr++) {
        int r = rr * 8 + warp;
        float s = warp_sumsq_x32(&gA[(size_t)r * ND], lane);
        if (lane == 0) An[r] = s;
    }

    // ---- build bf16 A buffer [row][d], padded rows ----
    #pragma unroll
    for (int i = 0; i < (TM * ND / 2) / NTHREADS; i++) {
        int idx = tid + i * NTHREADS;
        int r = idx >> 7, w = idx & 127;
        float2 v = *(const float2*)(gA + (size_t)r * ND + 2 * w);
        Au[r * (A_STRIDE_H / 2) + w] = bf2(v.x, v.y);
    }
    __syncthreads();

    // ---- staging mapping: thread owns (code kk, 16-d half h2) ----
    const int kk = tid & 127;
    const int h2 = tid >> 7;
    const int doff = h2 * 16;
    const float* wb = W + (size_t)kk * ND + doff;

    float4 c0 = ((const float4*)wb)[0], c1 = ((const float4*)wb)[1];
    float4 c2 = ((const float4*)wb)[2], c3 = ((const float4*)wb)[3];
    int pbuf = 0;

    for (int ntile = 0; ntile < NTILES; ntile++) {
        float accf[2][4][4];
        #pragma unroll
        for (int a = 0; a < 2; a++)
            #pragma unroll
            for (int b = 0; b < 4; b++)
                #pragma unroll
                for (int c = 0; c < 4; c++) accf[a][b][c] = 0.f;

        for (int dchunk = 0; dchunk < 8; dchunk++) {
            const int s  = ntile * 8 + dchunk;
            const int sn = (s + 1 < 64) ? s + 1 : s;
            const float4* np = (const float4*)(W + (size_t)((sn >> 3) * TILEN + kk) * ND
                                               + (sn & 7) * 32 + doff);
            float4 n0 = np[0], n1 = np[1], n2 = np[2], n3 = np[3];

            // store current stage (bf16, code-major rows)
            uint4* bs = (uint4*)(smem + B_OFF + pbuf * B_STAGE_BYTES) + (kk * 5 + h2 * 2);
            bs[0] = make_uint4(bf2(c0.x, c0.y), bf2(c0.z, c0.w),
                               bf2(c1.x, c1.y), bf2(c1.z, c1.w));
            bs[1] = make_uint4(bf2(c2.x, c2.y), bf2(c2.z, c2.w),
                               bf2(c3.x, c3.y), bf2(c3.z, c3.w));
            __syncthreads();

            const uint32_t bB = sbase + B_OFF + pbuf * B_STAGE_BYTES;
            #pragma unroll
            for (int kg = 0; kg < 2; kg++) {
                const int kq = dchunk * 2 + kg;          // k16 group in [0,16)
                uint32_t a0[4], a1[4], bql[4], bqh[4];
                uint32_t aaddr = sbase + (uint32_t)(mg * 32 + (lane & 15)) * (A_STRIDE_H * 2)
                               + (uint32_t)(kq * 16 + (lane >> 4) * 8) * 2;
                ldsm4(a0, aaddr);
                ldsm4(a1, aaddr + 16 * (A_STRIDE_H * 2));
                uint32_t baddr = bB
                               + (uint32_t)(ng * 32 + ((lane & 16) >> 1) + (lane & 7)) * (B_STRIDE_H * 2)
                               + (uint32_t)(kg * 16 + (lane & 8)) * 2;
                ldsm4(bql, baddr);
                ldsm4(bqh, baddr + 16 * (B_STRIDE_H * 2));
                mma_bf16(accf[0][0], a0, bql[0], bql[1]);
                mma_bf16(accf[1][0], a1, bql[0], bql[1]);
                mma_bf16(accf[0][1], a0, bql[2], bql[3]);
                mma_bf16(accf[1][1], a1, bql[2], bql[3]);
                mma_bf16(accf[0][2], a0, bqh[0], bqh[1]);
                mma_bf16(accf[1][2], a1, bqh[0], bqh[1]);
                mma_bf16(accf[0][3], a0, bqh[2], bqh[3]);
                mma_bf16(accf[1][3], a1, bqh[2], bqh[3]);
            }
            pbuf ^= 1;
            c0 = n0; c1 = n1; c2 = n2; c3 = n3;
        }

        // ---- per-ntile epilogue: screen + candidate push (adaptive bound) ----
        #pragma unroll
        for (int mt = 0; mt < 2; mt++) {
            #pragma unroll
            for (int h = 0; h < 2; h++) {
                int row = 32 * mg + 16 * mt + lr + 8 * h;
                float A  = An[row];
                // bound: |screen-exact| per dist <= 2*(2^-8*1.01)*sqrt(An*NsMax)+slop
                float ee = 0.0159f * sqrtf(A * nsM) + 0.25f;  // = 2*e_dist
                float dl[8]; float m = 3.4e38f;
                #pragma unroll
                for (int ns = 0; ns < 4; ns++)
                    #pragma unroll
                    for (int c = 0; c < 2; c++) {
                        float dv = A - 2.f * accf[mt][ns][2 * h + c]
                                 + Ns[ntile * TILEN + ng * 32 + ns * 8 + 2 * lc + c];
                        dl[ns * 2 + c] = dv;
                        m = fminf(m, dv);
                    }
                float m2 = m;
                m2 = fminf(m2, __shfl_xor_sync(0xffffffffu, m2, 1));
                m2 = fminf(m2, __shfl_xor_sync(0xffffffffu, m2, 2));
                float rm  = __uint_as_float(runmin[row]);     // racy = conservative
                float thr = fminf(m2, rm) + ee;
                #pragma unroll
                for (int e = 0; e < 8; e++) {
                    if (dl[e] <= thr) {
                        int col = ntile * TILEN + ng * 32 + (e >> 1) * 8 + 2 * lc + (e & 1);
                        int slot = atomicAdd(&cnt[row], 1);
                        if (slot < CAP)
                            cand[row * CAP + slot] =
                                (__float_as_uint(fmaxf(dl[e], 0.f)) & 0xFFFFFC00u)
                                | (uint32_t)col;
                    }
                }
                if (lc == 0)
                    atomicMin(runmin + row, __float_as_uint(fmaxf(m2, 0.f)));
            }
        }
    }
    __syncthreads();

    // ---- exact rescore, 4-way parallel per row (bit-identical chain) ----
    {
        int row = tid & (TM - 1), sl = tid >> 6;
        float A = An[row];
        float thrF = __uint_as_float(runmin[row]) + (0.0159f * sqrtf(A * nsM) + 0.25f);
        int n = cnt[row]; if (n > CAP) n = CAP;
        float bv = 3.4e38f; int bi = 1 << 30;
        const float* ar = gA + (size_t)row * ND;
        for (int s = sl; s < n; s += 4) {
            uint32_t u = cand[row * CAP + s];
            if (__uint_as_float(u & 0xFFFFFC00u) > thrF) continue;
            int col = (int)(u & 1023u);
            const float* wr = W + (size_t)col * ND;
            float acc = 0.f;
            #pragma unroll 8
            for (int d = 0; d < ND; d++) acc = __fmaf_rn(ar[d], wr[d], acc);
            float de = __fadd_rn(__fsub_rn(A, __fmul_rn(2.f, acc)), Ns[col]);
            if (de < bv || (de == bv && col < bi)) { bv = de; bi = col; }
        }
        pbv[row * 4 + sl] = bv;
        pbi[row * 4 + sl] = bi;
    }
    __syncthreads();
    if (tid < TM) {
        float bv = pbv[tid * 4]; int bi = pbi[tid * 4];
        #pragma unroll
        for (int t = 1; t < 4; t++) {
            float v = pbv[tid * 4 + t]; int ii = pbi[tid * 4 + t];
            if (v < bv || (v == bv && ii < bi)) { bv = v; bi = ii; }
        }
        if (bi >= NK) bi = 0;               // unreachable by construction
        RowIdx[tid] = bi;
        if (write_idx) {
            int nn = row0 + tid;
            int b = nn >> 11;               // T = 2048
            int t = nn & (NT - 1);
            idx_out[(size_t)b * NL * NT + (size_t)l * NT + t] = (float)bi;
        }
    }
    __syncthreads();

    // ---- residual -= gathered code ----
    {
        float4*       gout = (float4*)(g_res + (size_t)row0 * ND);
        const float4* gin  = (const float4*)gA;
        #pragma unroll
        for (int it = 0; it < (TM * (ND / 4)) / NTHREADS; it++) {
            int e   = tid + it * NTHREADS;
            int row = e >> 6;
            int d4  = e & 63;
            float4 w4 = *(const float4*)(W + (size_t)RowIdx[row] * ND + 4 * d4);
            float4 a4 = gin[e];
            gout[e] = make_float4(__fsub_rn(a4.x, w4.x), __fsub_rn(a4.y, w4.y),
                                  __fsub_rn(a4.z, w4.z), __fsub_rn(a4.w, w4.w));
        }
    }
}

// ---------------------------------------------------------------- launch
extern "C" void kernel_launch(void* const* d_in, const int* in_sizes, int n_in,
                              void* d_out, int out_size) {
    const float* x  = (const float*)d_in[0];
    const float* cb = (const float*)d_in[1];
    if (n_in >= 2 && in_sizes[0] == NL * NK * ND && in_sizes[1] == NB * ND * NT) {
        const float* t = x; x = cb; cb = t;
    }
    float* out = (float*)d_out;
    int write_idx = (out_size >= NOUT + NIDX) ? 1 : 0;

    cudaFuncSetAttribute(vq_layer_kernel,
                         cudaFuncAttributeMaxDynamicSharedMemorySize, SMEM_BYTES);

    norms_kernel<<<(NL * NK * 32 + 255) / 256, 256>>>(cb);

    dim3 tb(32, 8);
    tin_kernel<<<dim3(NT / 32, ND / 32, NB), tb>>>(x);

    for (int l = 0; l < NL; l++)
        vq_layer_kernel<<<NVEC / TM, NTHREADS, SMEM_BYTES>>>(cb, out + NOUT, l, write_idx);

    tout_kernel<<<dim3(NT / 32, ND / 32, NB), tb>>>(x, out);
}

// round 8
// speedup vs baseline: 1.3535x; 1.3535x over previous
#include <cuda_runtime.h>
#include <cstdint>

#define NB 32
#define ND 256
#define NT 2048
#define NL 8
#define NK 1024
#define NVEC (NB*NT)
#define NOUT (NB*ND*NT)
#define NIDX (NB*NL*NT)

#define TM 128                       // rows per CTA
#define NTHREADS 512
#define TILEN 128                    // codes per ntile
#define NTILES (NK/TILEN)            // 8
#define CAP 36

// SMEM layout (bytes):
#define ATF_OFF 0                    // A bf16 fragments: 4096 uint4 = 65536
#define B_OFF   65536                // staged B frags: 2 x 512 uint4 = 16384
#define NS_OFF  81920                // 1024 f32
#define AN_OFF  86016                // 128 f32
#define RM_OFF  86528                // 128 u32
#define CNT_OFF 87040                // 128 i32
#define RI_OFF  87552                // 128 i32
#define CD_OFF  88064                // 128*CAP u32 = 18432
#define PBV_OFF 106496               // 128*4 f32
#define PBI_OFF 108544               // 128*4 i32
#define SMEM_BYTES 110592            // x2 CTAs = 221184 <= 228KB/SM

// Scratch (static device allocations are the sanctioned workaround)
__device__ float    g_res[(size_t)NVEC * ND];
__device__ float    g_norms[NL * NK];
__device__ unsigned g_nsmax[NL];     // per-layer max |W|^2 (float bits)

// ---------------------------------------------------------------- helpers
__device__ __forceinline__ uint32_t bf2(float lo, float hi) {
    uint32_t r; asm("cvt.rn.bf16x2.f32 %0, %1, %2;" : "=r"(r) : "f"(hi), "f"(lo));
    return r;
}
__device__ __forceinline__ void mma_bf16(float* c, const uint32_t* a,
                                         uint32_t b0, uint32_t b1) {
    asm volatile(
        "mma.sync.aligned.m16n8k16.row.col.f32.bf16.bf16.f32 "
        "{%0,%1,%2,%3}, {%4,%5,%6,%7}, {%8,%9}, {%0,%1,%2,%3};"
        : "+f"(c[0]), "+f"(c[1]), "+f"(c[2]), "+f"(c[3])
        : "r"(a[0]), "r"(a[1]), "r"(a[2]), "r"(a[3]), "r"(b0), "r"(b1));
}

// XLA-style warp row-reduce (mul then add, NO fma), xor-butterfly tree.
__device__ __forceinline__ float warp_sumsq_x32(const float* __restrict__ p, int lane) {
    float s = 0.f;
    #pragma unroll
    for (int i = 0; i < ND / 32; i++) {
        float v = p[lane + 32 * i];
        s = __fadd_rn(s, __fmul_rn(v, v));
    }
    #pragma unroll
    for (int o = 16; o; o >>= 1)
        s = __fadd_rn(s, __shfl_xor_sync(0xffffffffu, s, o));
    return s;
}

// ---------------------------------------------------------------- codebook norms
__global__ void norms_kernel(const float* __restrict__ cb) {
    int w    = (blockIdx.x * blockDim.x + threadIdx.x) >> 5;
    int lane = threadIdx.x & 31;
    if (w >= NL * NK) return;
    float s = warp_sumsq_x32(cb + (size_t)w * ND, lane);
    if (lane == 0) {
        g_norms[w] = s;
        atomicMax(&g_nsmax[w >> 10], __float_as_uint(s));  // >0: uint order == float order
    }
}

// ---------------------------------------------------------------- x (B,D,T) -> res (N,D)
__global__ void tin_kernel(const float* __restrict__ x) {
    __shared__ float tile[32][33];
    int b  = blockIdx.z;
    int d0 = blockIdx.y * 32, t0 = blockIdx.x * 32;
    int tx = threadIdx.x, ty = threadIdx.y;
    #pragma unroll
    for (int i = 0; i < 32; i += 8)
        tile[ty + i][tx] = x[((size_t)b * ND + d0 + ty + i) * NT + t0 + tx];
    __syncthreads();
    #pragma unroll
    for (int i = 0; i < 32; i += 8)
        g_res[((size_t)(b * NT + t0 + ty + i)) * ND + d0 + tx] = tile[tx][ty + i];
}

// ---------------------------------------------------------------- out = x - res
__global__ void tout_kernel(const float* __restrict__ x, float* __restrict__ out) {
    __shared__ float tile[32][33];
    int b  = blockIdx.z;
    int d0 = blockIdx.y * 32, t0 = blockIdx.x * 32;
    int tx = threadIdx.x, ty = threadIdx.y;
    #pragma unroll
    for (int i = 0; i < 32; i += 8)
        tile[ty + i][tx] = g_res[((size_t)(b * NT + t0 + ty + i)) * ND + d0 + tx];
    __syncthreads();
    size_t base = (size_t)b * ND * NT;
    #pragma unroll
    for (int i = 0; i < 32; i += 8) {
        size_t o = base + (size_t)(d0 + ty + i) * NT + t0 + tx;
        out[o] = __fsub_rn(x[o], tile[tx][ty + i]);
    }
}

// ---------------------------------------------------------------- one RVQ layer
__global__ void __launch_bounds__(NTHREADS, 2) vq_layer_kernel(
    const float* __restrict__ codebooks,
    float* __restrict__ idx_out,
    int l, int write_idx)
{
    extern __shared__ char smem[];
    uint4*    Atf4   = (uint4*)(smem + ATF_OFF);      // A bf16 fragments
    uint4*    Bs4    = (uint4*)(smem + B_OFF);        // staged B fragments (x2)
    float*    Ns     = (float*)(smem + NS_OFF);
    float*    An     = (float*)(smem + AN_OFF);
    uint32_t* runmin = (uint32_t*)(smem + RM_OFF);
    int*      cnt    = (int*)(smem + CNT_OFF);
    int*      RowIdx = (int*)(smem + RI_OFF);
    uint32_t* cand   = (uint32_t*)(smem + CD_OFF);
    float*    pbv    = (float*)(smem + PBV_OFF);
    int*      pbi    = (int*)(smem + PBI_OFF);

    const float* W  = codebooks + (size_t)l * NK * ND;
    const int row0  = blockIdx.x * TM;
    const float* gA = g_res + (size_t)row0 * ND;
    const int tid   = threadIdx.x;
    const int lane  = tid & 31;
    const int warp  = tid >> 5;
    const int mg    = warp & 3;        // M-group (32 rows)
    const int ng    = warp >> 2;       // N-group (32 cols within ntile)
    const int lr    = lane >> 2, lc = lane & 3;
    const float nsM = __uint_as_float(g_nsmax[l]);

    for (int i = tid; i < NK; i += NTHREADS) Ns[i] = g_norms[l * NK + i];
    if (tid < TM) { cnt[tid] = 0; runmin[tid] = 0x7F7FFFFFu; }

    // ---- |r|^2 per row, XLA reduce order ----
    #pragma unroll
    for (int rr = 0; rr < TM / 16; rr++) {
        int r = rr * 16 + warp;
        float s = warp_sumsq_x32(&gA[(size_t)r * ND], lane);
        if (lane == 0) An[r] = s;
    }

    // ---- pack A as bf16 m16n8k16 fragments (once per layer) ----
    // slot s: lane=s&31, kq=(s>>5)&15, mt=(s>>9)&1, mgi=s>>10
    #pragma unroll
    for (int i = 0; i < 4096 / NTHREADS; i++) {
        int s   = tid + i * NTHREADS;
        int lb  = s & 31, kq = (s >> 5) & 15, mt = (s >> 9) & 1, mgi = s >> 10;
        int r   = mgi * 32 + mt * 16 + (lb >> 2);
        int k0  = kq * 16 + (lb & 3) * 2;
        float2 x0 = *(const float2*)(gA + (size_t)r * ND + k0);
        float2 x1 = *(const float2*)(gA + (size_t)(r + 8) * ND + k0);
        float2 x2 = *(const float2*)(gA + (size_t)r * ND + k0 + 8);
        float2 x3 = *(const float2*)(gA + (size_t)(r + 8) * ND + k0 + 8);
        Atf4[s] = make_uint4(bf2(x0.x, x0.y), bf2(x1.x, x1.y),
                             bf2(x2.x, x2.y), bf2(x3.x, x3.y));
    }
    __syncthreads();

    // ---- staging ids: thread owns one B-fragment slot per stage ----
    // slot = ((kg*2+p)*4+ng_s)*32 + l  == tid
    const int l_s  = tid & 31;
    const int ng_s = (tid >> 5) & 3;
    const int p_s  = (tid >> 7) & 1;
    const int kg_s = tid >> 8;
    const int c0   = ng_s * 32 + p_s * 16 + (l_s >> 2);   // code within tile
    const int kb   = kg_s * 16 + (l_s & 3) * 2;           // d within stage

    int pbuf = 0;
    for (int ntile = 0; ntile < NTILES; ntile++) {
        float accf[2][4][4];
        #pragma unroll
        for (int a = 0; a < 2; a++)
            #pragma unroll
            for (int b = 0; b < 4; b++)
                #pragma unroll
                for (int c = 0; c < 4; c++) accf[a][b][c] = 0.f;

        for (int dchunk = 0; dchunk < 8; dchunk++) {
            // stage B fragment: 4 x LDG.64 -> cvt -> 1 x STS.128
            {
                const float* w0 = W + (size_t)(ntile * TILEN + c0) * ND
                                    + dchunk * 32 + kb;
                const float* w1 = w0 + 8 * ND;            // c0 + 8
                float2 q0 = *(const float2*)(w0);
                float2 q1 = *(const float2*)(w0 + 8);
                float2 q2 = *(const float2*)(w1);
                float2 q3 = *(const float2*)(w1 + 8);
                Bs4[pbuf * 512 + tid] = make_uint4(bf2(q0.x, q0.y), bf2(q1.x, q1.y),
                                                   bf2(q2.x, q2.y), bf2(q3.x, q3.y));
            }
            __syncthreads();

            #pragma unroll
            for (int kg = 0; kg < 2; kg++) {
                const int kq = dchunk * 2 + kg;
                uint4 A0 = Atf4[((mg * 2 + 0) * 16 + kq) * 32 + lane];
                uint4 A1 = Atf4[((mg * 2 + 1) * 16 + kq) * 32 + lane];
                uint32_t af0[4] = {A0.x, A0.y, A0.z, A0.w};
                uint32_t af1[4] = {A1.x, A1.y, A1.z, A1.w};
                #pragma unroll
                for (int p = 0; p < 2; p++) {
                    uint4 B = Bs4[pbuf * 512 + ((kg * 2 + p) * 4 + ng) * 32 + lane];
                    mma_bf16(accf[0][2 * p],     af0, B.x, B.y);
                    mma_bf16(accf[1][2 * p],     af1, B.x, B.y);
                    mma_bf16(accf[0][2 * p + 1], af0, B.z, B.w);
                    mma_bf16(accf[1][2 * p + 1], af1, B.z, B.w);
                }
            }
            pbuf ^= 1;
        }

        // ---- per-ntile epilogue: screen + candidate push (adaptive bound) ----
        #pragma unroll
        for (int mt = 0; mt < 2; mt++) {
            #pragma unroll
            for (int h = 0; h < 2; h++) {
                int row = 32 * mg + 16 * mt + lr + 8 * h;
                float A  = An[row];
                float ee = 0.0159f * sqrtf(A * nsM) + 0.25f;
                float dl[8]; float m = 3.4e38f;
                #pragma unroll
                for (int ns = 0; ns < 4; ns++)
                    #pragma unroll
                    for (int c = 0; c < 2; c++) {
                        float dv = A - 2.f * accf[mt][ns][2 * h + c]
                                 + Ns[ntile * TILEN + ng * 32 + ns * 8 + 2 * lc + c];
                        dl[ns * 2 + c] = dv;
                        m = fminf(m, dv);
                    }
                float m2 = m;
                m2 = fminf(m2, __shfl_xor_sync(0xffffffffu, m2, 1));
                m2 = fminf(m2, __shfl_xor_sync(0xffffffffu, m2, 2));
                float rm  = __uint_as_float(runmin[row]);    // racy = conservative
                float thr = fminf(m2, rm) + ee;
                #pragma unroll
                for (int e = 0; e < 8; e++) {
                    if (dl[e] <= thr) {
                        int col = ntile * TILEN + ng * 32 + (e >> 1) * 8 + 2 * lc + (e & 1);
                        int slot = atomicAdd(&cnt[row], 1);
                        if (slot < CAP)
                            cand[row * CAP + slot] =
                                (__float_as_uint(fmaxf(dl[e], 0.f)) & 0xFFFFFC00u)
                                | (uint32_t)col;
                    }
                }
                if (lc == 0)
                    atomicMin(runmin + row, __float_as_uint(fmaxf(m2, 0.f)));
            }
        }
    }
    __syncthreads();

    // ---- exact rescore, 4-way per row (bit-identical chain); overflow -> full scan ----
    {
        int row = tid & (TM - 1), sl = tid >> 7;
        float A = An[row];
        float thrF = __uint_as_float(runmin[row]) + (0.0159f * sqrtf(A * nsM) + 0.25f);
        int n = cnt[row];
        float bv = 3.4e38f; int bi = 1 << 30;
        const float* ar = gA + (size_t)row * ND;
        if (n <= CAP) {
            for (int s = sl; s < n; s += 4) {
                uint32_t u = cand[row * CAP + s];
                if (__uint_as_float(u & 0xFFFFFC00u) > thrF) continue;
                int col = (int)(u & 1023u);
                const float* wr = W + (size_t)col * ND;
                float acc = 0.f;
                #pragma unroll 8
                for (int d = 0; d < ND; d++) acc = __fmaf_rn(ar[d], wr[d], acc);
                float de = __fadd_rn(__fsub_rn(A, __fmul_rn(2.f, acc)), Ns[col]);
                if (de < bv || (de == bv && col < bi)) { bv = de; bi = col; }
            }
        } else {
            // candidate list overflowed: guaranteed-exact full scan (rare)
            for (int col = sl; col < NK; col += 4) {
                const float* wr = W + (size_t)col * ND;
                float acc = 0.f;
                #pragma unroll 8
                for (int d = 0; d < ND; d++) acc = __fmaf_rn(ar[d], wr[d], acc);
                float de = __fadd_rn(__fsub_rn(A, __fmul_rn(2.f, acc)), Ns[col]);
                if (de < bv || (de == bv && col < bi)) { bv = de; bi = col; }
            }
        }
        pbv[row * 4 + sl] = bv;
        pbi[row * 4 + sl] = bi;
    }
    __syncthreads();
    if (tid < TM) {
        float bv = pbv[tid * 4]; int bi = pbi[tid * 4];
        #pragma unroll
        for (int t = 1; t < 4; t++) {
            float v = pbv[tid * 4 + t]; int ii = pbi[tid * 4 + t];
            if (v < bv || (v == bv && ii < bi)) { bv = v; bi = ii; }
        }
        if (bi >= NK) bi = 0;               // unreachable by construction
        RowIdx[tid] = bi;
        if (write_idx) {
            int nn = row0 + tid;
            int b = nn >> 11;               // T = 2048
            int t = nn & (NT - 1);
            idx_out[(size_t)b * NL * NT + (size_t)l * NT + t] = (float)bi;
        }
    }
    __syncthreads();

    // ---- residual -= gathered code ----
    {
        float4*       gout = (float4*)(g_res + (size_t)row0 * ND);
        const float4* gin  = (const float4*)gA;
        #pragma unroll
        for (int it = 0; it < (TM * (ND / 4)) / NTHREADS; it++) {
            int e   = tid + it * NTHREADS;
            int row = e >> 6;
            int d4  = e & 63;
            float4 w4 = *(const float4*)(W + (size_t)RowIdx[row] * ND + 4 * d4);
            float4 a4 = gin[e];
            gout[e] = make_float4(__fsub_rn(a4.x, w4.x), __fsub_rn(a4.y, w4.y),
                                  __fsub_rn(a4.z, w4.z), __fsub_rn(a4.w, w4.w));
        }
    }
}

// ---------------------------------------------------------------- launch
extern "C" void kernel_launch(void* const* d_in, const int* in_sizes, int n_in,
                              void* d_out, int out_size) {
    const float* x  = (const float*)d_in[0];
    const float* cb = (const float*)d_in[1];
    if (n_in >= 2 && in_sizes[0] == NL * NK * ND && in_sizes[1] == NB * ND * NT) {
        const float* t = x; x = cb; cb = t;
    }
    float* out = (float*)d_out;
    int write_idx = (out_size >= NOUT + NIDX) ? 1 : 0;

    cudaFuncSetAttribute(vq_layer_kernel,
                         cudaFuncAttributeMaxDynamicSharedMemorySize, SMEM_BYTES);

    norms_kernel<<<(NL * NK * 32 + 255) / 256, 256>>>(cb);

    dim3 tb(32, 8);
    tin_kernel<<<dim3(NT / 32, ND / 32, NB), tb>>>(x);

    for (int l = 0; l < NL; l++)
        vq_layer_kernel<<<NVEC / TM, NTHREADS, SMEM_BYTES>>>(cb, out + NOUT, l, write_idx);

    tout_kernel<<<dim3(NT / 32, ND / 32, NB), tb>>>(x, out);
}

// round 10
// speedup vs baseline: 1.5369x; 1.1355x over previous
#include <cuda_runtime.h>
#include <cstdint>

#define NB 32
#define ND 256
#define NT 2048
#define NL 8
#define NK 1024
#define NVEC (NB*NT)
#define NOUT (NB*ND*NT)
#define NIDX (NB*NL*NT)

#define TM 128                       // rows per CTA
#define NTHREADS 256
#define TILEN 128                    // codes per ntile
#define NTILES (NK/TILEN)            // 8
#define NSTG 64                      // total stages (ntile x dchunk)
#define CAP 32

// SMEM layout (bytes)
#define ATF_OFF 0                    // A bf16 fragments: 4096 uint4 = 65536
#define B_OFF   65536                // staged B frags: 2 x 512 uint4 = 16384
#define NS_OFF  81920                // 1024 f32
#define AN_OFF  86016                // 128 f32
#define RM_OFF  86528                // 128 u32
#define CNT_OFF 87040                // 128 i32
#define RI_OFF  87552                // 128 i32
#define CD_OFF  88064                // 128*CAP u32 = 16384
#define PBV_OFF 104448               // 128*2 f32
#define PBI_OFF 105472               // 128*2 i32
#define SMEM_BYTES 106496            // x2 CTAs = 212992 <= 228KB/SM

// Scratch (static device allocations are the sanctioned workaround)
__device__ float    g_res[(size_t)NVEC * ND];
__device__ float    g_norms[NL * NK];
__device__ unsigned g_nsmax[NL];
__device__ uint4    g_wpack[NL * NSTG * 512];   // fragment-major bf16 codebook (4MB)

// ---------------------------------------------------------------- helpers
__device__ __forceinline__ uint32_t bf2(float lo, float hi) {
    uint32_t r; asm("cvt.rn.bf16x2.f32 %0, %1, %2;" : "=r"(r) : "f"(hi), "f"(lo));
    return r;
}
__device__ __forceinline__ void mma_bf16(float* c, const uint32_t* a,
                                         uint32_t b0, uint32_t b1) {
    asm volatile(
        "mma.sync.aligned.m16n8k16.row.col.f32.bf16.bf16.f32 "
        "{%0,%1,%2,%3}, {%4,%5,%6,%7}, {%8,%9}, {%0,%1,%2,%3};"
        : "+f"(c[0]), "+f"(c[1]), "+f"(c[2]), "+f"(c[3])
        : "r"(a[0]), "r"(a[1]), "r"(a[2]), "r"(a[3]), "r"(b0), "r"(b1));
}
__device__ __forceinline__ void cpasync16(uint32_t dst, const void* src) {
    asm volatile("cp.async.cg.shared.global [%0], [%1], 16;"
                 :: "r"(dst), "l"(src) : "memory");
}
#define CP_COMMIT() asm volatile("cp.async.commit_group;" ::: "memory")
#define CP_WAIT0()  asm volatile("cp.async.wait_group 0;" ::: "memory")

// XLA-style warp row-reduce (mul then add, NO fma), xor-butterfly tree.
__device__ __forceinline__ float warp_sumsq_x32(const float* __restrict__ p, int lane) {
    float s = 0.f;
    #pragma unroll
    for (int i = 0; i < ND / 32; i++) {
        float v = p[lane + 32 * i];
        s = __fadd_rn(s, __fmul_rn(v, v));
    }
    #pragma unroll
    for (int o = 16; o; o >>= 1)
        s = __fadd_rn(s, __shfl_xor_sync(0xffffffffu, s, o));
    return s;
}

// ---------------------------------------------------------------- codebook norms
__global__ void norms_kernel(const float* __restrict__ cb) {
    int w    = (blockIdx.x * blockDim.x + threadIdx.x) >> 5;
    int lane = threadIdx.x & 31;
    if (w >= NL * NK) return;
    float s = warp_sumsq_x32(cb + (size_t)w * ND, lane);
    if (lane == 0) {
        g_norms[w] = s;
        atomicMax(&g_nsmax[w >> 10], __float_as_uint(s));
    }
}

// ---------------------------------------------------------------- pack codebook -> bf16 fragments
// slot within stage = ((kg*2+ng)*4+pp)*32 + lane; stage = ntile*8+dchunk
__global__ void pack_kernel(const float* __restrict__ cb) {
    int gid  = blockIdx.x * blockDim.x + threadIdx.x;   // 0 .. NL*64*512-1
    int lane = gid & 31;
    int s16  = (gid >> 5) & 15;
    int pp   = s16 & 3, ng = (s16 >> 2) & 1, kg = s16 >> 3;
    int st   = (gid >> 9) & 63;
    int l    = gid >> 15;
    int code = (st >> 3) * TILEN + ng * 64 + pp * 16 + (lane >> 2);
    int d    = (st & 7) * 32 + kg * 16 + (lane & 3) * 2;
    const float* w = cb + ((size_t)l * NK + code) * ND + d;
    uint4 v;
    v.x = bf2(w[0], w[1]);
    v.y = bf2(w[8], w[9]);
    v.z = bf2(w[8 * ND], w[8 * ND + 1]);
    v.w = bf2(w[8 * ND + 8], w[8 * ND + 9]);
    g_wpack[gid] = v;
}

// ---------------------------------------------------------------- x (B,D,T) -> res (N,D)
__global__ void tin_kernel(const float* __restrict__ x) {
    __shared__ float tile[32][33];
    int b  = blockIdx.z;
    int d0 = blockIdx.y * 32, t0 = blockIdx.x * 32;
    int tx = threadIdx.x, ty = threadIdx.y;
    #pragma unroll
    for (int i = 0; i < 32; i += 8)
        tile[ty + i][tx] = x[((size_t)b * ND + d0 + ty + i) * NT + t0 + tx];
    __syncthreads();
    #pragma unroll
    for (int i = 0; i < 32; i += 8)
        g_res[((size_t)(b * NT + t0 + ty + i)) * ND + d0 + tx] = tile[tx][ty + i];
}

// ---------------------------------------------------------------- out = x - res
__global__ void tout_kernel(const float* __restrict__ x, float* __restrict__ out) {
    __shared__ float tile[32][33];
    int b  = blockIdx.z;
    int d0 = blockIdx.y * 32, t0 = blockIdx.x * 32;
    int tx = threadIdx.x, ty = threadIdx.y;
    #pragma unroll
    for (int i = 0; i < 32; i += 8)
        tile[ty + i][tx] = g_res[((size_t)(b * NT + t0 + ty + i)) * ND + d0 + tx];
    __syncthreads();
    size_t base = (size_t)b * ND * NT;
    #pragma unroll
    for (int i = 0; i < 32; i += 8) {
        size_t o = base + (size_t)(d0 + ty + i) * NT + t0 + tx;
        out[o] = __fsub_rn(x[o], tile[tx][ty + i]);
    }
}

// ---------------------------------------------------------------- one RVQ layer
__global__ void __launch_bounds__(NTHREADS, 2) vq_layer_kernel(
    const float* __restrict__ codebooks,
    float* __restrict__ idx_out,
    int l, int write_idx)
{
    extern __shared__ char smem[];
    uint4*    Atf4   = (uint4*)(smem + ATF_OFF);
    uint4*    Bs4    = (uint4*)(smem + B_OFF);
    float*    Ns     = (float*)(smem + NS_OFF);
    float*    An     = (float*)(smem + AN_OFF);
    uint32_t* runmin = (uint32_t*)(smem + RM_OFF);
    int*      cnt    = (int*)(smem + CNT_OFF);
    int*      RowIdx = (int*)(smem + RI_OFF);
    uint32_t* cand   = (uint32_t*)(smem + CD_OFF);
    float*    pbv    = (float*)(smem + PBV_OFF);
    int*      pbi    = (int*)(smem + PBI_OFF);

    uint32_t sbase;
    asm("{ .reg .u64 t; cvta.to.shared.u64 t, %1; cvt.u32.u64 %0, t; }"
        : "=r"(sbase) : "l"(smem));

    const float* W  = codebooks + (size_t)l * NK * ND;
    const int row0  = blockIdx.x * TM;
    const float* gA = g_res + (size_t)row0 * ND;
    const int tid   = threadIdx.x;
    const int lane  = tid & 31;
    const int warp  = tid >> 5;
    const int mg    = warp & 3;        // M-group (32 rows)
    const int ng    = warp >> 2;       // N-group (64 cols within ntile)
    const int lr    = lane >> 2, lc = lane & 3;
    const float nsM = __uint_as_float(g_nsmax[l]);

    for (int i = tid; i < NK; i += NTHREADS) Ns[i] = g_norms[l * NK + i];
    if (tid < TM) { cnt[tid] = 0; runmin[tid] = 0x7F7FFFFFu; }

    // ---- |r|^2 per row, XLA reduce order ----
    #pragma unroll
    for (int rr = 0; rr < TM / 8; rr++) {
        int r = rr * 8 + warp;
        float s = warp_sumsq_x32(&gA[(size_t)r * ND], lane);
        if (lane == 0) An[r] = s;
    }

    // ---- pack A as bf16 m16n8k16 fragments (once per layer) ----
    #pragma unroll
    for (int i = 0; i < 4096 / NTHREADS; i++) {
        int s   = tid + i * NTHREADS;
        int lb  = s & 31, kq = (s >> 5) & 15, mt = (s >> 9) & 1, mgi = s >> 10;
        int r   = mgi * 32 + mt * 16 + (lb >> 2);
        int k0  = kq * 16 + (lb & 3) * 2;
        float2 x0 = *(const float2*)(gA + (size_t)r * ND + k0);
        float2 x1 = *(const float2*)(gA + (size_t)(r + 8) * ND + k0);
        float2 x2 = *(const float2*)(gA + (size_t)r * ND + k0 + 8);
        float2 x3 = *(const float2*)(gA + (size_t)(r + 8) * ND + k0 + 8);
        Atf4[s] = make_uint4(bf2(x0.x, x0.y), bf2(x1.x, x1.y),
                             bf2(x2.x, x2.y), bf2(x3.x, x3.y));
    }

    // ---- prologue: async-stage B stage 0 ----
    const uint4* wp = (const uint4*)g_wpack + (size_t)l * NSTG * 512;
    {
        uint32_t dst = sbase + B_OFF;
        cpasync16(dst + tid * 16, wp + tid);
        cpasync16(dst + (tid + 256) * 16, wp + tid + 256);
        CP_COMMIT();
    }

    float accf[2][8][4];
    for (int t = 0; t < NSTG; t++) {
        const int ntile = t >> 3, dchunk = t & 7;
        const int pbuf  = t & 1;
        if (dchunk == 0) {
            #pragma unroll
            for (int a = 0; a < 2; a++)
                #pragma unroll
                for (int b = 0; b < 8; b++)
                    #pragma unroll
                    for (int c = 0; c < 4; c++) accf[a][b][c] = 0.f;
        }

        CP_WAIT0();              // stage t landed (only outstanding group)
        __syncthreads();         // visible to all; all readers of buf^1 are done

        if (t + 1 < NSTG) {      // overlap: stage t+1 copies during compute(t)
            uint32_t dst = sbase + B_OFF + ((t + 1) & 1) * 8192;
            const uint4* src = wp + (size_t)(t + 1) * 512;
            cpasync16(dst + tid * 16, src + tid);
            cpasync16(dst + (tid + 256) * 16, src + tid + 256);
            CP_COMMIT();
        }

        #pragma unroll
        for (int kg = 0; kg < 2; kg++) {
            const int kq = dchunk * 2 + kg;
            uint4 A0 = Atf4[((mg * 2 + 0) * 16 + kq) * 32 + lane];
            uint4 A1 = Atf4[((mg * 2 + 1) * 16 + kq) * 32 + lane];
            uint32_t af0[4] = {A0.x, A0.y, A0.z, A0.w};
            uint32_t af1[4] = {A1.x, A1.y, A1.z, A1.w};
            #pragma unroll
            for (int pp = 0; pp < 4; pp++) {
                uint4 B = Bs4[pbuf * 512 + ((kg * 2 + ng) * 4 + pp) * 32 + lane];
                mma_bf16(accf[0][pp * 2],     af0, B.x, B.y);
                mma_bf16(accf[1][pp * 2],     af1, B.x, B.y);
                mma_bf16(accf[0][pp * 2 + 1], af0, B.z, B.w);
                mma_bf16(accf[1][pp * 2 + 1], af1, B.z, B.w);
            }
        }

        // ---- per-ntile epilogue: screen + candidate push (adaptive bound) ----
        if (dchunk == 7) {
            #pragma unroll
            for (int mt = 0; mt < 2; mt++) {
                #pragma unroll
                for (int h = 0; h < 2; h++) {
                    int row = 32 * mg + 16 * mt + lr + 8 * h;
                    float A  = An[row];
                    float ee = 0.0159f * sqrtf(A * nsM) + 0.25f;
                    float m = 3.4e38f;
                    #pragma unroll
                    for (int j = 0; j < 8; j++)
                        #pragma unroll
                        for (int c = 0; c < 2; c++) {
                            int col = ntile * TILEN + ng * 64 + (j >> 1) * 16
                                    + (j & 1) * 8 + 2 * lc + c;
                            float dv = A - 2.f * accf[mt][j][2 * h + c] + Ns[col];
                            m = fminf(m, dv);
                        }
                    float m2 = m;
                    m2 = fminf(m2, __shfl_xor_sync(0xffffffffu, m2, 1));
                    m2 = fminf(m2, __shfl_xor_sync(0xffffffffu, m2, 2));
                    float rm  = __uint_as_float(runmin[row]);    // racy = conservative
                    float thr = fminf(m2, rm) + ee;
                    #pragma unroll
                    for (int j = 0; j < 8; j++)
                        #pragma unroll
                        for (int c = 0; c < 2; c++) {
                            int col = ntile * TILEN + ng * 64 + (j >> 1) * 16
                                    + (j & 1) * 8 + 2 * lc + c;
                            float dv = A - 2.f * accf[mt][j][2 * h + c] + Ns[col];
                            if (dv <= thr) {
                                int slot = atomicAdd(&cnt[row], 1);
                                if (slot < CAP)
                                    cand[row * CAP + slot] =
                                        (__float_as_uint(fmaxf(dv, 0.f)) & 0xFFFFFC00u)
                                        | (uint32_t)col;
                            }
                        }
                    if (lc == 0)
                        atomicMin(runmin + row, __float_as_uint(fmaxf(m2, 0.f)));
                }
            }
        }
    }
    __syncthreads();

    // ---- exact rescore, 2-way per row (bit-identical chain); overflow -> full scan ----
    {
        int row = tid & (TM - 1), sl = tid >> 7;
        float A = An[row];
        float thrF = __uint_as_float(runmin[row]) + (0.0159f * sqrtf(A * nsM) + 0.25f);
        int n = cnt[row];
        float bv = 3.4e38f; int bi = 1 << 30;
        const float* ar = gA + (size_t)row * ND;
        if (n <= CAP) {
            for (int s = sl; s < n; s += 2) {
                uint32_t u = cand[row * CAP + s];
                if (__uint_as_float(u & 0xFFFFFC00u) > thrF) continue;
                int col = (int)(u & 1023u);
                const float* wr = W + (size_t)col * ND;
                float acc = 0.f;
                #pragma unroll 8
                for (int d = 0; d < ND; d++) acc = __fmaf_rn(ar[d], wr[d], acc);
                float de = __fadd_rn(__fsub_rn(A, __fmul_rn(2.f, acc)), Ns[col]);
                if (de < bv || (de == bv && col < bi)) { bv = de; bi = col; }
            }
        } else {
            for (int col = sl; col < NK; col += 2) {
                const float* wr = W + (size_t)col * ND;
                float acc = 0.f;
                #pragma unroll 8
                for (int d = 0; d < ND; d++) acc = __fmaf_rn(ar[d], wr[d], acc);
                float de = __fadd_rn(__fsub_rn(A, __fmul_rn(2.f, acc)), Ns[col]);
                if (de < bv || (de == bv && col < bi)) { bv = de; bi = col; }
            }
        }
        pbv[row * 2 + sl] = bv;
        pbi[row * 2 + sl] = bi;
    }
    __syncthreads();
    if (tid < TM) {
        float bv = pbv[tid * 2]; int bi = pbi[tid * 2];
        float v = pbv[tid * 2 + 1]; int ii = pbi[tid * 2 + 1];
        if (v < bv || (v == bv && ii < bi)) { bv = v; bi = ii; }
        if (bi >= NK) bi = 0;               // unreachable by construction
        RowIdx[tid] = bi;
        if (write_idx) {
            int nn = row0 + tid;
            int b = nn >> 11;               // T = 2048
            int t = nn & (NT - 1);
            idx_out[(size_t)b * NL * NT + (size_t)l * NT + t] = (float)bi;
        }
    }
    __syncthreads();

    // ---- residual -= gathered code ----
    {
        float4*       gout = (float4*)(g_res + (size_t)row0 * ND);
        const float4* gin  = (const float4*)gA;
        #pragma unroll
        for (int it = 0; it < (TM * (ND / 4)) / NTHREADS; it++) {
            int e   = tid + it * NTHREADS;
            int row = e >> 6;
            int d4  = e & 63;
            float4 w4 = *(const float4*)(W + (size_t)RowIdx[row] * ND + 4 * d4);
            float4 a4 = gin[e];
            gout[e] = make_float4(__fsub_rn(a4.x, w4.x), __fsub_rn(a4.y, w4.y),
                                  __fsub_rn(a4.z, w4.z), __fsub_rn(a4.w, w4.w));
        }
    }
}

// ---------------------------------------------------------------- launch
extern "C" void kernel_launch(void* const* d_in, const int* in_sizes, int n_in,
                              void* d_out, int out_size) {
    const float* x  = (const float*)d_in[0];
    const float* cb = (const float*)d_in[1];
    if (n_in >= 2 && in_sizes[0] == NL * NK * ND && in_sizes[1] == NB * ND * NT) {
        const float* t = x; x = cb; cb = t;
    }
    float* out = (float*)d_out;
    int write_idx = (out_size >= NOUT + NIDX) ? 1 : 0;

    cudaFuncSetAttribute(vq_layer_kernel,
                         cudaFuncAttributeMaxDynamicSharedMemorySize, SMEM_BYTES);

    norms_kernel<<<(NL * NK * 32 + 255) / 256, 256>>>(cb);
    pack_kernel<<<NL * NSTG * 512 / 256, 256>>>(cb);

    dim3 tb(32, 8);
    tin_kernel<<<dim3(NT / 32, ND / 32, NB), tb>>>(x);

    for (int l = 0; l < NL; l++)
        vq_layer_kernel<<<NVEC / TM, NTHREADS, SMEM_BYTES>>>(cb, out + NOUT, l, write_idx);

    tout_kernel<<<dim3(NT / 32, ND / 32, NB), tb>>>(x, out);
}

// round 11
// speedup vs baseline: 1.5851x; 1.0314x over previous
#include <cuda_runtime.h>
#include <cstdint>

#define NB 32
#define ND 256
#define NT 2048
#define NL 8
#define NK 1024
#define NVEC (NB*NT)
#define NOUT (NB*ND*NT)
#define NIDX (NB*NL*NT)

#define TM 128                       // rows per CTA
#define NTHREADS 256
#define TILEN 128                    // codes per ntile
#define NTILES (NK/TILEN)            // 8
#define NSTG 64                      // total stages (ntile x dchunk)
#define CAP 32

// SMEM layout (bytes) — no B staging buffers anymore
#define ATF_OFF 0                    // A bf16 fragments: 4096 uint4 = 65536
#define NS_OFF  65536                // 1024 f32
#define AN_OFF  69632                // 128 f32
#define RM_OFF  70144                // 128 u32
#define CNT_OFF 70656                // 128 i32
#define RI_OFF  71168                // 128 i32
#define CD_OFF  71680                // 128*CAP u32 = 16384
#define PBV_OFF 88064                // 128*2 f32
#define PBI_OFF 89088                // 128*2 i32
#define SMEM_BYTES 90112             // x2 CTAs = 176KB <= 228KB/SM

// Scratch (static device allocations are the sanctioned workaround)
__device__ float    g_res[(size_t)NVEC * ND];
__device__ float    g_norms[NL * NK];
__device__ unsigned g_nsmax[NL];
__device__ uint4    g_wpack[NL * NSTG * 512];   // fragment-major bf16 codebook (4MB)

// ---------------------------------------------------------------- helpers
__device__ __forceinline__ uint32_t bf2(float lo, float hi) {
    uint32_t r; asm("cvt.rn.bf16x2.f32 %0, %1, %2;" : "=r"(r) : "f"(hi), "f"(lo));
    return r;
}
__device__ __forceinline__ void mma_bf16(float* c, const uint32_t* a,
                                         uint32_t b0, uint32_t b1) {
    asm volatile(
        "mma.sync.aligned.m16n8k16.row.col.f32.bf16.bf16.f32 "
        "{%0,%1,%2,%3}, {%4,%5,%6,%7}, {%8,%9}, {%0,%1,%2,%3};"
        : "+f"(c[0]), "+f"(c[1]), "+f"(c[2]), "+f"(c[3])
        : "r"(a[0]), "r"(a[1]), "r"(a[2]), "r"(a[3]), "r"(b0), "r"(b1));
}

// XLA-style warp row-reduce (mul then add, NO fma), xor-butterfly tree.
__device__ __forceinline__ float warp_sumsq_x32(const float* __restrict__ p, int lane) {
    float s = 0.f;
    #pragma unroll
    for (int i = 0; i < ND / 32; i++) {
        float v = p[lane + 32 * i];
        s = __fadd_rn(s, __fmul_rn(v, v));
    }
    #pragma unroll
    for (int o = 16; o; o >>= 1)
        s = __fadd_rn(s, __shfl_xor_sync(0xffffffffu, s, o));
    return s;
}

// ---------------------------------------------------------------- codebook norms
__global__ void norms_kernel(const float* __restrict__ cb) {
    int w    = (blockIdx.x * blockDim.x + threadIdx.x) >> 5;
    int lane = threadIdx.x & 31;
    if (w >= NL * NK) return;
    float s = warp_sumsq_x32(cb + (size_t)w * ND, lane);
    if (lane == 0) {
        g_norms[w] = s;
        atomicMax(&g_nsmax[w >> 10], __float_as_uint(s));
    }
}

// ---------------------------------------------------------------- pack codebook -> bf16 fragments
// slot within stage = ((kg*2+ngh)*4+pp)*32 + lane; stage = ntile*8+dchunk
__global__ void pack_kernel(const float* __restrict__ cb) {
    int gid  = blockIdx.x * blockDim.x + threadIdx.x;   // 0 .. NL*64*512-1
    int lane = gid & 31;
    int s16  = (gid >> 5) & 15;
    int pp   = s16 & 3, ng = (s16 >> 2) & 1, kg = s16 >> 3;
    int st   = (gid >> 9) & 63;
    int l    = gid >> 15;
    int code = (st >> 3) * TILEN + ng * 64 + pp * 16 + (lane >> 2);
    int d    = (st & 7) * 32 + kg * 16 + (lane & 3) * 2;
    const float* w = cb + ((size_t)l * NK + code) * ND + d;
    uint4 v;
    v.x = bf2(w[0], w[1]);
    v.y = bf2(w[8], w[9]);
    v.z = bf2(w[8 * ND], w[8 * ND + 1]);
    v.w = bf2(w[8 * ND + 8], w[8 * ND + 9]);
    g_wpack[gid] = v;
}

// ---------------------------------------------------------------- x (B,D,T) -> res (N,D)
__global__ void tin_kernel(const float* __restrict__ x) {
    __shared__ float tile[32][33];
    int b  = blockIdx.z;
    int d0 = blockIdx.y * 32, t0 = blockIdx.x * 32;
    int tx = threadIdx.x, ty = threadIdx.y;
    #pragma unroll
    for (int i = 0; i < 32; i += 8)
        tile[ty + i][tx] = x[((size_t)b * ND + d0 + ty + i) * NT + t0 + tx];
    __syncthreads();
    #pragma unroll
    for (int i = 0; i < 32; i += 8)
        g_res[((size_t)(b * NT + t0 + ty + i)) * ND + d0 + tx] = tile[tx][ty + i];
}

// ---------------------------------------------------------------- out = x - res
__global__ void tout_kernel(const float* __restrict__ x, float* __restrict__ out) {
    __shared__ float tile[32][33];
    int b  = blockIdx.z;
    int d0 = blockIdx.y * 32, t0 = blockIdx.x * 32;
    int tx = threadIdx.x, ty = threadIdx.y;
    #pragma unroll
    for (int i = 0; i < 32; i += 8)
        tile[ty + i][tx] = g_res[((size_t)(b * NT + t0 + ty + i)) * ND + d0 + tx];
    __syncthreads();
    size_t base = (size_t)b * ND * NT;
    #pragma unroll
    for (int i = 0; i < 32; i += 8) {
        size_t o = base + (size_t)(d0 + ty + i) * NT + t0 + tx;
        out[o] = __fsub_rn(x[o], tile[tx][ty + i]);
    }
}

// ---------------------------------------------------------------- one RVQ layer
__global__ void __launch_bounds__(NTHREADS, 2) vq_layer_kernel(
    const float* __restrict__ codebooks,
    float* __restrict__ idx_out,
    int l, int write_idx)
{
    extern __shared__ char smem[];
    uint4*    Atf4   = (uint4*)(smem + ATF_OFF);
    float*    Ns     = (float*)(smem + NS_OFF);
    float*    An     = (float*)(smem + AN_OFF);
    uint32_t* runmin = (uint32_t*)(smem + RM_OFF);
    int*      cnt    = (int*)(smem + CNT_OFF);
    int*      RowIdx = (int*)(smem + RI_OFF);
    uint32_t* cand   = (uint32_t*)(smem + CD_OFF);
    float*    pbv    = (float*)(smem + PBV_OFF);
    int*      pbi    = (int*)(smem + PBI_OFF);

    const float* W  = codebooks + (size_t)l * NK * ND;
    const int row0  = blockIdx.x * TM;
    const float* gA = g_res + (size_t)row0 * ND;
    const int tid   = threadIdx.x;
    const int lane  = tid & 31;
    const int warp  = tid >> 5;
    const int mg    = warp & 1;        // M-group (64 rows)
    const int ng    = warp >> 1;       // N-group (32 cols within ntile)
    const int lr    = lane >> 2, lc = lane & 3;
    const float nsM = __uint_as_float(g_nsmax[l]);

    for (int i = tid; i < NK; i += NTHREADS) Ns[i] = g_norms[l * NK + i];
    if (tid < TM) { cnt[tid] = 0; runmin[tid] = 0x7F7FFFFFu; }

    // ---- |r|^2 per row, XLA reduce order ----
    #pragma unroll
    for (int rr = 0; rr < TM / 8; rr++) {
        int r = rr * 8 + warp;
        float s = warp_sumsq_x32(&gA[(size_t)r * ND], lane);
        if (lane == 0) An[r] = s;
    }

    // ---- pack A as bf16 m16n8k16 fragments (once per layer) ----
    #pragma unroll
    for (int i = 0; i < 4096 / NTHREADS; i++) {
        int s   = tid + i * NTHREADS;
        int lb  = s & 31, kq = (s >> 5) & 15, mt = (s >> 9) & 1, mgi = s >> 10;
        int r   = mgi * 32 + mt * 16 + (lb >> 2);
        int k0  = kq * 16 + (lb & 3) * 2;
        float2 x0 = *(const float2*)(gA + (size_t)r * ND + k0);
        float2 x1 = *(const float2*)(gA + (size_t)(r + 8) * ND + k0);
        float2 x2 = *(const float2*)(gA + (size_t)r * ND + k0 + 8);
        float2 x3 = *(const float2*)(gA + (size_t)(r + 8) * ND + k0 + 8);
        Atf4[s] = make_uint4(bf2(x0.x, x0.y), bf2(x1.x, x1.y),
                             bf2(x2.x, x2.y), bf2(x3.x, x3.y));
    }
    __syncthreads();     // A buffer ready; NO barriers in mainloop after this

    // ---- per-warp B fragment slot addresses in g_wpack ----
    const uint4* wp = (const uint4*)g_wpack + (size_t)l * NSTG * 512;
    const int ngh = ng >> 1, ngl = ng & 1;
    int sb[4];
    #pragma unroll
    for (int kg = 0; kg < 2; kg++)
        #pragma unroll
        for (int p = 0; p < 2; p++)
            sb[kg * 2 + p] = ((kg * 2 + ngh) * 4 + ngl * 2 + p) * 32 + lane;

    uint4 Bc[4], Bn[4];
    #pragma unroll
    for (int q = 0; q < 4; q++) Bc[q] = wp[sb[q]];   // stage 0

    float accf[4][4][4];
    for (int t = 0; t < NSTG; t++) {
        const int ntile = t >> 3, dchunk = t & 7;
        if (dchunk == 0) {
            #pragma unroll
            for (int a = 0; a < 4; a++)
                #pragma unroll
                for (int b = 0; b < 4; b++)
                    #pragma unroll
                    for (int c = 0; c < 4; c++) accf[a][b][c] = 0.f;
        }
        // register double-buffer: prefetch B(t+1) while computing t
        {
            const uint4* wn = wp + (size_t)((t + 1 < NSTG) ? t + 1 : t) * 512;
            #pragma unroll
            for (int q = 0; q < 4; q++) Bn[q] = wn[sb[q]];
        }

        #pragma unroll
        for (int kg = 0; kg < 2; kg++) {
            const int kq = dchunk * 2 + kg;
            uint4 Af[4];
            #pragma unroll
            for (int mt = 0; mt < 4; mt++)
                Af[mt] = Atf4[((mg * 4 + mt) * 16 + kq) * 32 + lane];
            #pragma unroll
            for (int mt = 0; mt < 4; mt++) {
                uint32_t a[4] = {Af[mt].x, Af[mt].y, Af[mt].z, Af[mt].w};
                #pragma unroll
                for (int ns = 0; ns < 4; ns++) {
                    uint4 B = Bc[kg * 2 + (ns >> 1)];
                    uint32_t b0 = (ns & 1) ? B.z : B.x;
                    uint32_t b1 = (ns & 1) ? B.w : B.y;
                    mma_bf16(accf[mt][ns], a, b0, b1);
                }
            }
        }
        #pragma unroll
        for (int q = 0; q < 4; q++) Bc[q] = Bn[q];

        // ---- per-ntile epilogue: screen + candidate push (adaptive bound) ----
        if (dchunk == 7) {
            #pragma unroll
            for (int mt = 0; mt < 4; mt++) {
                #pragma unroll
                for (int h = 0; h < 2; h++) {
                    int row = mg * 64 + mt * 16 + lr + 8 * h;
                    float A  = An[row];
                    float ee = 0.0159f * sqrtf(A * nsM) + 0.25f;
                    float m = 3.4e38f;
                    #pragma unroll
                    for (int ns = 0; ns < 4; ns++)
                        #pragma unroll
                        for (int c = 0; c < 2; c++) {
                            int col = ntile * TILEN + ng * 32 + (ns >> 1) * 16
                                    + (ns & 1) * 8 + 2 * lc + c;
                            float dv = A - 2.f * accf[mt][ns][2 * h + c] + Ns[col];
                            m = fminf(m, dv);
                        }
                    float m2 = m;
                    m2 = fminf(m2, __shfl_xor_sync(0xffffffffu, m2, 1));
                    m2 = fminf(m2, __shfl_xor_sync(0xffffffffu, m2, 2));
                    float rm  = __uint_as_float(runmin[row]);    // racy = conservative
                    float thr = fminf(m2, rm) + ee;
                    #pragma unroll
                    for (int ns = 0; ns < 4; ns++)
                        #pragma unroll
                        for (int c = 0; c < 2; c++) {
                            int col = ntile * TILEN + ng * 32 + (ns >> 1) * 16
                                    + (ns & 1) * 8 + 2 * lc + c;
                            float dv = A - 2.f * accf[mt][ns][2 * h + c] + Ns[col];
                            if (dv <= thr) {
                                int slot = atomicAdd(&cnt[row], 1);
                                if (slot < CAP)
                                    cand[row * CAP + slot] =
                                        (__float_as_uint(fmaxf(dv, 0.f)) & 0xFFFFFC00u)
                                        | (uint32_t)col;
                            }
                        }
                    if (lc == 0)
                        atomicMin(runmin + row, __float_as_uint(fmaxf(m2, 0.f)));
                }
            }
        }
    }
    __syncthreads();

    // ---- exact rescore, 2-way per row (bit-identical chain); overflow -> full scan ----
    {
        int row = tid & (TM - 1), sl = tid >> 7;
        float A = An[row];
        float thrF = __uint_as_float(runmin[row]) + (0.0159f * sqrtf(A * nsM) + 0.25f);
        int n = cnt[row];
        float bv = 3.4e38f; int bi = 1 << 30;
        const float* ar = gA + (size_t)row * ND;
        if (n <= CAP) {
            for (int s = sl; s < n; s += 2) {
                uint32_t u = cand[row * CAP + s];
                if (__uint_as_float(u & 0xFFFFFC00u) > thrF) continue;
                int col = (int)(u & 1023u);
                const float* wr = W + (size_t)col * ND;
                float acc = 0.f;
                #pragma unroll 8
                for (int d = 0; d < ND; d++) acc = __fmaf_rn(ar[d], wr[d], acc);
                float de = __fadd_rn(__fsub_rn(A, __fmul_rn(2.f, acc)), Ns[col]);
                if (de < bv || (de == bv && col < bi)) { bv = de; bi = col; }
            }
        } else {
            for (int col = sl; col < NK; col += 2) {
                const float* wr = W + (size_t)col * ND;
                float acc = 0.f;
                #pragma unroll 8
                for (int d = 0; d < ND; d++) acc = __fmaf_rn(ar[d], wr[d], acc);
                float de = __fadd_rn(__fsub_rn(A, __fmul_rn(2.f, acc)), Ns[col]);
                if (de < bv || (de == bv && col < bi)) { bv = de; bi = col; }
            }
        }
        pbv[row * 2 + sl] = bv;
        pbi[row * 2 + sl] = bi;
    }
    __syncthreads();
    if (tid < TM) {
        float bv = pbv[tid * 2]; int bi = pbi[tid * 2];
        float v = pbv[tid * 2 + 1]; int ii = pbi[tid * 2 + 1];
        if (v < bv || (v == bv && ii < bi)) { bv = v; bi = ii; }
        if (bi >= NK) bi = 0;               // unreachable by construction
        RowIdx[tid] = bi;
        if (write_idx) {
            int nn = row0 + tid;
            int b = nn >> 11;               // T = 2048
            int t = nn & (NT - 1);
            idx_out[(size_t)b * NL * NT + (size_t)l * NT + t] = (float)bi;
        }
    }
    __syncthreads();

    // ---- residual -= gathered code ----
    {
        float4*       gout = (float4*)(g_res + (size_t)row0 * ND);
        const float4* gin  = (const float4*)gA;
        #pragma unroll
        for (int it = 0; it < (TM * (ND / 4)) / NTHREADS; it++) {
            int e   = tid + it * NTHREADS;
            int row = e >> 6;
            int d4  = e & 63;
            float4 w4 = *(const float4*)(W + (size_t)RowIdx[row] * ND + 4 * d4);
            float4 a4 = gin[e];
            gout[e] = make_float4(__fsub_rn(a4.x, w4.x), __fsub_rn(a4.y, w4.y),
                                  __fsub_rn(a4.z, w4.z), __fsub_rn(a4.w, w4.w));
        }
    }
}

// ---------------------------------------------------------------- launch
extern "C" void kernel_launch(void* const* d_in, const int* in_sizes, int n_in,
                              void* d_out, int out_size) {
    const float* x  = (const float*)d_in[0];
    const float* cb = (const float*)d_in[1];
    if (n_in >= 2 && in_sizes[0] == NL * NK * ND && in_sizes[1] == NB * ND * NT) {
        const float* t = x; x = cb; cb = t;
    }
    float* out = (float*)d_out;
    int write_idx = (out_size >= NOUT + NIDX) ? 1 : 0;

    cudaFuncSetAttribute(vq_layer_kernel,
                         cudaFuncAttributeMaxDynamicSharedMemorySize, SMEM_BYTES);

    norms_kernel<<<(NL * NK * 32 + 255) / 256, 256>>>(cb);
    pack_kernel<<<NL * NSTG * 512 / 256, 256>>>(cb);

    dim3 tb(32, 8);
    tin_kernel<<<dim3(NT / 32, ND / 32, NB), tb>>>(x);

    for (int l = 0; l < NL; l++)
        vq_layer_kernel<<<NVEC / TM, NTHREADS, SMEM_BYTES>>>(cb, out + NOUT, l, write_idx);

    tout_kernel<<<dim3(NT / 32, ND / 32, NB), tb>>>(x, out);
}

// round 12
// speedup vs baseline: 1.6896x; 1.0659x over previous
#include <cuda_runtime.h>
#include <cstdint>

#define NB 32
#define ND 256
#define NT 2048
#define NL 8
#define NK 1024
#define NVEC (NB*NT)
#define NOUT (NB*ND*NT)
#define NIDX (NB*NL*NT)

#define TM 128                       // rows per CTA
#define NTHREADS 256
#define TILEN 128                    // codes per ntile
#define NTILES (NK/TILEN)            // 8
#define NSTG 64                      // total stages (ntile x dchunk)
#define CAP 32

// SMEM layout (bytes) — no B staging buffers
#define ATF_OFF 0                    // A bf16 fragments: 4096 uint4 = 65536
#define NS_OFF  65536                // 1024 f32
#define AN_OFF  69632                // 128 f32
#define RM_OFF  70144                // 128 u32
#define CNT_OFF 70656                // 128 i32
#define RI_OFF  71168                // 128 i32
#define CD_OFF  71680                // 128*CAP u32 = 16384
#define PBV_OFF 88064                // 128*2 f32
#define PBI_OFF 89088                // 128*2 i32
#define SMEM_BYTES 90112             // x2 CTAs = 176KB <= 228KB/SM

// Scratch (static device allocations are the sanctioned workaround)
__device__ float    g_res[(size_t)NVEC * ND];
__device__ float    g_norms[NL * NK];
__device__ unsigned g_nsmax[NL];
__device__ uint4    g_wpack[NL * NSTG * 512];   // fragment-major bf16 codebook (4MB)

typedef unsigned long long ull;

// ---------------------------------------------------------------- helpers
__device__ __forceinline__ uint32_t bf2(float lo, float hi) {
    uint32_t r; asm("cvt.rn.bf16x2.f32 %0, %1, %2;" : "=r"(r) : "f"(hi), "f"(lo));
    return r;
}
__device__ __forceinline__ void mma_bf16(float* c, const uint32_t* a,
                                         uint32_t b0, uint32_t b1) {
    asm volatile(
        "mma.sync.aligned.m16n8k16.row.col.f32.bf16.bf16.f32 "
        "{%0,%1,%2,%3}, {%4,%5,%6,%7}, {%8,%9}, {%0,%1,%2,%3};"
        : "+f"(c[0]), "+f"(c[1]), "+f"(c[2]), "+f"(c[3])
        : "r"(a[0]), "r"(a[1]), "r"(a[2]), "r"(a[3]), "r"(b0), "r"(b1));
}
__device__ __forceinline__ ull pack2(float a, float b) {
    ull r; asm("mov.b64 %0, {%1, %2};" : "=l"(r) : "f"(a), "f"(b)); return r;
}
__device__ __forceinline__ float2 unpack2(ull v) {
    float2 r; asm("mov.b64 {%0, %1}, %2;" : "=f"(r.x), "=f"(r.y) : "l"(v)); return r;
}
__device__ __forceinline__ ull ffma2(ull a, ull b, ull c) {
    ull d; asm("fma.rn.f32x2 %0, %1, %2, %3;" : "=l"(d) : "l"(a), "l"(b), "l"(c));
    return d;
}
__device__ __forceinline__ ull fadd2(ull a, ull b) {
    ull d; asm("add.rn.f32x2 %0, %1, %2;" : "=l"(d) : "l"(a), "l"(b));
    return d;
}

// XLA-style warp row-reduce (mul then add, NO fma), xor-butterfly tree.
__device__ __forceinline__ float warp_sumsq_x32(const float* __restrict__ p, int lane) {
    float s = 0.f;
    #pragma unroll
    for (int i = 0; i < ND / 32; i++) {
        float v = p[lane + 32 * i];
        s = __fadd_rn(s, __fmul_rn(v, v));
    }
    #pragma unroll
    for (int o = 16; o; o >>= 1)
        s = __fadd_rn(s, __shfl_xor_sync(0xffffffffu, s, o));
    return s;
}

// ---------------------------------------------------------------- codebook norms
__global__ void norms_kernel(const float* __restrict__ cb) {
    int w    = (blockIdx.x * blockDim.x + threadIdx.x) >> 5;
    int lane = threadIdx.x & 31;
    if (w >= NL * NK) return;
    float s = warp_sumsq_x32(cb + (size_t)w * ND, lane);
    if (lane == 0) {
        g_norms[w] = s;
        atomicMax(&g_nsmax[w >> 10], __float_as_uint(s));
    }
}

// ---------------------------------------------------------------- pack codebook -> bf16 fragments
// slot within stage = ((kg*2+ngh)*4+pp)*32 + lane; stage = ntile*8+dchunk
__global__ void pack_kernel(const float* __restrict__ cb) {
    int gid  = blockIdx.x * blockDim.x + threadIdx.x;   // 0 .. NL*64*512-1
    int lane = gid & 31;
    int s16  = (gid >> 5) & 15;
    int pp   = s16 & 3, ng = (s16 >> 2) & 1, kg = s16 >> 3;
    int st   = (gid >> 9) & 63;
    int l    = gid >> 15;
    int code = (st >> 3) * TILEN + ng * 64 + pp * 16 + (lane >> 2);
    int d    = (st & 7) * 32 + kg * 16 + (lane & 3) * 2;
    const float* w = cb + ((size_t)l * NK + code) * ND + d;
    uint4 v;
    v.x = bf2(w[0], w[1]);
    v.y = bf2(w[8], w[9]);
    v.z = bf2(w[8 * ND], w[8 * ND + 1]);
    v.w = bf2(w[8 * ND + 8], w[8 * ND + 9]);
    g_wpack[gid] = v;
}

// ---------------------------------------------------------------- x (B,D,T) -> res (N,D)
__global__ void tin_kernel(const float* __restrict__ x) {
    __shared__ float tile[32][33];
    int b  = blockIdx.z;
    int d0 = blockIdx.y * 32, t0 = blockIdx.x * 32;
    int tx = threadIdx.x, ty = threadIdx.y;
    #pragma unroll
    for (int i = 0; i < 32; i += 8)
        tile[ty + i][tx] = x[((size_t)b * ND + d0 + ty + i) * NT + t0 + tx];
    __syncthreads();
    #pragma unroll
    for (int i = 0; i < 32; i += 8)
        g_res[((size_t)(b * NT + t0 + ty + i)) * ND + d0 + tx] = tile[tx][ty + i];
}

// ---------------------------------------------------------------- out = x - res
__global__ void tout_kernel(const float* __restrict__ x, float* __restrict__ out) {
    __shared__ float tile[32][33];
    int b  = blockIdx.z;
    int d0 = blockIdx.y * 32, t0 = blockIdx.x * 32;
    int tx = threadIdx.x, ty = threadIdx.y;
    #pragma unroll
    for (int i = 0; i < 32; i += 8)
        tile[ty + i][tx] = g_res[((size_t)(b * NT + t0 + ty + i)) * ND + d0 + tx];
    __syncthreads();
    size_t base = (size_t)b * ND * NT;
    #pragma unroll
    for (int i = 0; i < 32; i += 8) {
        size_t o = base + (size_t)(d0 + ty + i) * NT + t0 + tx;
        out[o] = __fsub_rn(x[o], tile[tx][ty + i]);
    }
}

// ---------------------------------------------------------------- one RVQ layer
__global__ void __launch_bounds__(NTHREADS, 2) vq_layer_kernel(
    const float* __restrict__ codebooks,
    float* __restrict__ idx_out,
    int l, int write_idx)
{
    extern __shared__ char smem[];
    uint4*    Atf4   = (uint4*)(smem + ATF_OFF);
    float*    Ns     = (float*)(smem + NS_OFF);
    float*    An     = (float*)(smem + AN_OFF);
    uint32_t* runmin = (uint32_t*)(smem + RM_OFF);
    int*      cnt    = (int*)(smem + CNT_OFF);
    int*      RowIdx = (int*)(smem + RI_OFF);
    uint32_t* cand   = (uint32_t*)(smem + CD_OFF);
    float*    pbv    = (float*)(smem + PBV_OFF);
    int*      pbi    = (int*)(smem + PBI_OFF);

    const float* W  = codebooks + (size_t)l * NK * ND;
    const int row0  = blockIdx.x * TM;
    const float* gA = g_res + (size_t)row0 * ND;
    const int tid   = threadIdx.x;
    const int lane  = tid & 31;
    const int warp  = tid >> 5;
    const int mg    = warp & 1;        // M-group (64 rows)
    const int ng    = warp >> 1;       // N-group (32 cols within ntile)
    const int lr    = lane >> 2, lc = lane & 3;
    const float nsM = __uint_as_float(g_nsmax[l]);

    for (int i = tid; i < NK; i += NTHREADS) Ns[i] = g_norms[l * NK + i];
    if (tid < TM) { cnt[tid] = 0; runmin[tid] = 0x7F7FFFFFu; }

    // ---- |r|^2 per row, XLA reduce order ----
    #pragma unroll
    for (int rr = 0; rr < TM / 8; rr++) {
        int r = rr * 8 + warp;
        float s = warp_sumsq_x32(&gA[(size_t)r * ND], lane);
        if (lane == 0) An[r] = s;
    }

    // ---- pack A as bf16 m16n8k16 fragments (once per layer) ----
    #pragma unroll
    for (int i = 0; i < 4096 / NTHREADS; i++) {
        int s   = tid + i * NTHREADS;
        int lb  = s & 31, kq = (s >> 5) & 15, mt = (s >> 9) & 1, mgi = s >> 10;
        int r   = mgi * 32 + mt * 16 + (lb >> 2);
        int k0  = kq * 16 + (lb & 3) * 2;
        float2 x0 = *(const float2*)(gA + (size_t)r * ND + k0);
        float2 x1 = *(const float2*)(gA + (size_t)(r + 8) * ND + k0);
        float2 x2 = *(const float2*)(gA + (size_t)r * ND + k0 + 8);
        float2 x3 = *(const float2*)(gA + (size_t)(r + 8) * ND + k0 + 8);
        Atf4[s] = make_uint4(bf2(x0.x, x0.y), bf2(x1.x, x1.y),
                             bf2(x2.x, x2.y), bf2(x3.x, x3.y));
    }
    __syncthreads();     // A buffer ready; NO barriers in mainloop after this

    // ---- per-warp B fragment slot addresses in g_wpack ----
    const uint4* wp = (const uint4*)g_wpack + (size_t)l * NSTG * 512;
    const int ngh = ng >> 1, ngl = ng & 1;
    int sb[4];
    #pragma unroll
    for (int kg = 0; kg < 2; kg++)
        #pragma unroll
        for (int p = 0; p < 2; p++)
            sb[kg * 2 + p] = ((kg * 2 + ngh) * 4 + ngl * 2 + p) * 32 + lane;

    const ull NEG2 = pack2(-2.f, -2.f);

    uint4 BA[4], BB[4];
    #pragma unroll
    for (int q = 0; q < 4; q++) BA[q] = wp[sb[q]];   // stage 0

    float accf[4][4][4];
    for (int t2 = 0; t2 < NSTG; t2 += 2) {
        if ((t2 & 7) == 0) {
            #pragma unroll
            for (int a = 0; a < 4; a++)
                #pragma unroll
                for (int b = 0; b < 4; b++)
                    #pragma unroll
                    for (int c = 0; c < 4; c++) accf[a][b][c] = 0.f;
        }
        // prefetch odd stage into BB, compute even stage from BA
        {
            const uint4* wn = wp + (size_t)(t2 + 1) * 512;
            #pragma unroll
            for (int q = 0; q < 4; q++) BB[q] = wn[sb[q]];
        }
        #pragma unroll
        for (int kg = 0; kg < 2; kg++) {
            const int kq = (t2 & 7) * 2 + kg;
            uint4 Af[4];
            #pragma unroll
            for (int mt = 0; mt < 4; mt++)
                Af[mt] = Atf4[((mg * 4 + mt) * 16 + kq) * 32 + lane];
            #pragma unroll
            for (int mt = 0; mt < 4; mt++) {
                uint32_t a[4] = {Af[mt].x, Af[mt].y, Af[mt].z, Af[mt].w};
                #pragma unroll
                for (int ns = 0; ns < 4; ns++) {
                    uint4 B = BA[kg * 2 + (ns >> 1)];
                    mma_bf16(accf[mt][ns], a, (ns & 1) ? B.z : B.x,
                                              (ns & 1) ? B.w : B.y);
                }
            }
        }
        // prefetch next even stage into BA, compute odd stage from BB
        {
            const uint4* wn = wp + (size_t)((t2 + 2 < NSTG) ? t2 + 2 : t2) * 512;
            #pragma unroll
            for (int q = 0; q < 4; q++) BA[q] = wn[sb[q]];
        }
        #pragma unroll
        for (int kg = 0; kg < 2; kg++) {
            const int kq = ((t2 + 1) & 7) * 2 + kg;
            uint4 Af[4];
            #pragma unroll
            for (int mt = 0; mt < 4; mt++)
                Af[mt] = Atf4[((mg * 4 + mt) * 16 + kq) * 32 + lane];
            #pragma unroll
            for (int mt = 0; mt < 4; mt++) {
                uint32_t a[4] = {Af[mt].x, Af[mt].y, Af[mt].z, Af[mt].w};
                #pragma unroll
                for (int ns = 0; ns < 4; ns++) {
                    uint4 B = BB[kg * 2 + (ns >> 1)];
                    mma_bf16(accf[mt][ns], a, (ns & 1) ? B.z : B.x,
                                              (ns & 1) ? B.w : B.y);
                }
            }
        }

        // ---- per-ntile epilogue (packed f32x2, single pass) ----
        if ((t2 & 7) == 6) {
            const int ntile = t2 >> 3;
            ull Ns2[4];
            #pragma unroll
            for (int ns = 0; ns < 4; ns++)
                Ns2[ns] = *(const ull*)&Ns[ntile * TILEN + ng * 32 + (ns >> 1) * 16
                                           + (ns & 1) * 8 + 2 * lc];
            #pragma unroll
            for (int mt = 0; mt < 4; mt++) {
                #pragma unroll
                for (int h = 0; h < 2; h++) {
                    int row = mg * 64 + mt * 16 + lr + 8 * h;
                    float A  = An[row];
                    float ee = 0.0159f * sqrtf(A * nsM) + 0.25f;
                    ull  A2  = pack2(A, A);
                    float dl[8]; float m = 3.4e38f;
                    #pragma unroll
                    for (int ns = 0; ns < 4; ns++) {
                        // dv = rn(rn(A - 2*acc) + Ns): fma(-2,acc,A) exact-equal
                        // to sub(A, mul(2,acc)) since 2*acc is exact.
                        ull acc2 = pack2(accf[mt][ns][2 * h], accf[mt][ns][2 * h + 1]);
                        float2 e = unpack2(fadd2(ffma2(acc2, NEG2, A2), Ns2[ns]));
                        dl[2 * ns] = e.x; dl[2 * ns + 1] = e.y;
                        m = fminf(m, fminf(e.x, e.y));
                    }
                    float m2 = fminf(m, __shfl_xor_sync(0xffffffffu, m, 1));
                    m2 = fminf(m2, __shfl_xor_sync(0xffffffffu, m2, 2));
                    float rm  = __uint_as_float(runmin[row]);    // racy = conservative
                    float thr = fminf(m2, rm) + ee;
                    #pragma unroll
                    for (int e8 = 0; e8 < 8; e8++) {
                        if (dl[e8] <= thr) {
                            int col = ntile * TILEN + ng * 32 + ((e8 >> 2) & 1) * 16
                                    + ((e8 >> 1) & 1) * 8 + 2 * lc + (e8 & 1);
                            int slot = atomicAdd(&cnt[row], 1);
                            if (slot < CAP)
                                cand[row * CAP + slot] =
                                    (__float_as_uint(fmaxf(dl[e8], 0.f)) & 0xFFFFFC00u)
                                    | (uint32_t)col;
                        }
                    }
                    if (lc == 0)
                        atomicMin(runmin + row, __float_as_uint(fmaxf(m2, 0.f)));
                }
            }
        }
    }
    __syncthreads();

    // ---- exact rescore, 2-way per row (bit-identical chain); overflow -> full scan ----
    {
        int row = tid & (TM - 1), sl = tid >> 7;
        float A = An[row];
        float thrF = __uint_as_float(runmin[row]) + (0.0159f * sqrtf(A * nsM) + 0.25f);
        int n = cnt[row];
        float bv = 3.4e38f; int bi = 1 << 30;
        const float* ar = gA + (size_t)row * ND;
        if (n <= CAP) {
            for (int s = sl; s < n; s += 2) {
                uint32_t u = cand[row * CAP + s];
                if (__uint_as_float(u & 0xFFFFFC00u) > thrF) continue;
                int col = (int)(u & 1023u);
                const float* wr = W + (size_t)col * ND;
                float acc = 0.f;
                #pragma unroll 8
                for (int d = 0; d < ND; d++) acc = __fmaf_rn(ar[d], wr[d], acc);
                float de = __fadd_rn(__fsub_rn(A, __fmul_rn(2.f, acc)), Ns[col]);
                if (de < bv || (de == bv && col < bi)) { bv = de; bi = col; }
            }
        } else {
            for (int col = sl; col < NK; col += 2) {
                const float* wr = W + (size_t)col * ND;
                float acc = 0.f;
                #pragma unroll 8
                for (int d = 0; d < ND; d++) acc = __fmaf_rn(ar[d], wr[d], acc);
                float de = __fadd_rn(__fsub_rn(A, __fmul_rn(2.f, acc)), Ns[col]);
                if (de < bv || (de == bv && col < bi)) { bv = de; bi = col; }
            }
        }
        pbv[row * 2 + sl] = bv;
        pbi[row * 2 + sl] = bi;
    }
    __syncthreads();
    if (tid < TM) {
        float bv = pbv[tid * 2]; int bi = pbi[tid * 2];
        float v = pbv[tid * 2 + 1]; int ii = pbi[tid * 2 + 1];
        if (v < bv || (v == bv && ii < bi)) { bv = v; bi = ii; }
        if (bi >= NK) bi = 0;               // unreachable by construction
        RowIdx[tid] = bi;
        if (write_idx) {
            int nn = row0 + tid;
            int b = nn >> 11;               // T = 2048
            int t = nn & (NT - 1);
            idx_out[(size_t)b * NL * NT + (size_t)l * NT + t] = (float)bi;
        }
    }
    __syncthreads();

    // ---- residual -= gathered code ----
    {
        float4*       gout = (float4*)(g_res + (size_t)row0 * ND);
        const float4* gin  = (const float4*)gA;
        #pragma unroll
        for (int it = 0; it < (TM * (ND / 4)) / NTHREADS; it++) {
            int e   = tid + it * NTHREADS;
            int row = e >> 6;
            int d4  = e & 63;
            float4 w4 = *(const float4*)(W + (size_t)RowIdx[row] * ND + 4 * d4);
            float4 a4 = gin[e];
            gout[e] = make_float4(__fsub_rn(a4.x, w4.x), __fsub_rn(a4.y, w4.y),
                                  __fsub_rn(a4.z, w4.z), __fsub_rn(a4.w, w4.w));
        }
    }
}

// ---------------------------------------------------------------- launch
extern "C" void kernel_launch(void* const* d_in, const int* in_sizes, int n_in,
                              void* d_out, int out_size) {
    const float* x  = (const float*)d_in[0];
    const float* cb = (const float*)d_in[1];
    if (n_in >= 2 && in_sizes[0] == NL * NK * ND && in_sizes[1] == NB * ND * NT) {
        const float* t = x; x = cb; cb = t;
    }
    float* out = (float*)d_out;
    int write_idx = (out_size >= NOUT + NIDX) ? 1 : 0;

    cudaFuncSetAttribute(vq_layer_kernel,
                         cudaFuncAttributeMaxDynamicSharedMemorySize, SMEM_BYTES);

    norms_kernel<<<(NL * NK * 32 + 255) / 256, 256>>>(cb);
    pack_kernel<<<NL * NSTG * 512 / 256, 256>>>(cb);

    dim3 tb(32, 8);
    tin_kernel<<<dim3(NT / 32, ND / 32, NB), tb>>>(x);

    for (int l = 0; l < NL; l++)
        vq_layer_kernel<<<NVEC / TM, NTHREADS, SMEM_BYTES>>>(cb, out + NOUT, l, write_idx);

    tout_kernel<<<dim3(NT / 32, ND / 32, NB), tb>>>(x, out);
}

// round 13
// speedup vs baseline: 3.3511x; 1.9833x over previous
#include <cuda_runtime.h>
#include <cstdint>

#define NB 32
#define ND 256
#define NT 2048
#define NL 8
#define NK 1024
#define NVEC (NB*NT)
#define NOUT (NB*ND*NT)
#define NIDX (NB*NL*NT)

#define TM 128                       // rows per CTA
#define NTHREADS 256
#define TILEN 128                    // codes per ntile
#define NTILES (NK/TILEN)            // 8
#define NSTG 64                      // total stages (ntile x dchunk)
#define CAP 32

// SMEM layout (bytes) — no B staging buffers
#define ATF_OFF 0                    // A bf16 fragments: 4096 uint4 = 65536
#define NS_OFF  65536                // 1024 f32
#define AN_OFF  69632                // 128 f32
#define RM_OFF  70144                // 128 u32
#define CNT_OFF 70656                // 128 i32
#define RI_OFF  71168                // 128 i32
#define CD_OFF  71680                // 128*CAP u32 = 16384
#define PBV_OFF 88064                // 128*2 f32
#define PBI_OFF 89088                // 128*2 i32
#define SMEM_BYTES 90112             // x2 CTAs = 176KB <= 228KB/SM

// Scratch (static device allocations are the sanctioned workaround)
__device__ float    g_res[(size_t)NVEC * ND];
__device__ float    g_norms[NL * NK];
__device__ unsigned g_nsmax[NL];
__device__ uint4    g_wpack[NL * NSTG * 512];   // fragment-major bf16 codebook (4MB)

typedef unsigned long long ull;

// ---------------------------------------------------------------- helpers
__device__ __forceinline__ uint32_t bf2(float lo, float hi) {
    uint32_t r; asm("cvt.rn.bf16x2.f32 %0, %1, %2;" : "=r"(r) : "f"(hi), "f"(lo));
    return r;
}
__device__ __forceinline__ void mma_bf16(float* c, const uint32_t* a,
                                         uint32_t b0, uint32_t b1) {
    asm volatile(
        "mma.sync.aligned.m16n8k16.row.col.f32.bf16.bf16.f32 "
        "{%0,%1,%2,%3}, {%4,%5,%6,%7}, {%8,%9}, {%0,%1,%2,%3};"
        : "+f"(c[0]), "+f"(c[1]), "+f"(c[2]), "+f"(c[3])
        : "r"(a[0]), "r"(a[1]), "r"(a[2]), "r"(a[3]), "r"(b0), "r"(b1));
}
__device__ __forceinline__ ull pack2(float a, float b) {
    ull r; asm("mov.b64 %0, {%1, %2};" : "=l"(r) : "f"(a), "f"(b)); return r;
}
__device__ __forceinline__ float2 unpack2(ull v) {
    float2 r; asm("mov.b64 {%0, %1}, %2;" : "=f"(r.x), "=f"(r.y) : "l"(v)); return r;
}
__device__ __forceinline__ ull ffma2(ull a, ull b, ull c) {
    ull d; asm("fma.rn.f32x2 %0, %1, %2, %3;" : "=l"(d) : "l"(a), "l"(b), "l"(c));
    return d;
}
__device__ __forceinline__ ull fadd2(ull a, ull b) {
    ull d; asm("add.rn.f32x2 %0, %1, %2;" : "=l"(d) : "l"(a), "l"(b));
    return d;
}

// XLA-style warp row-reduce (mul then add, NO fma), xor-butterfly tree.
__device__ __forceinline__ float warp_sumsq_x32(const float* __restrict__ p, int lane) {
    float s = 0.f;
    #pragma unroll
    for (int i = 0; i < ND / 32; i++) {
        float v = p[lane + 32 * i];
        s = __fadd_rn(s, __fmul_rn(v, v));
    }
    #pragma unroll
    for (int o = 16; o; o >>= 1)
        s = __fadd_rn(s, __shfl_xor_sync(0xffffffffu, s, o));
    return s;
}

// exact dot chain (ascending d, fmaf) — the validated rounding sequence,
// float4 loads only (same op order as scalar version).
__device__ __forceinline__ float dot_exact(const float4* __restrict__ a4,
                                           const float4* __restrict__ w4) {
    float acc = 0.f;
    #pragma unroll 8
    for (int q = 0; q < ND / 4; q++) {
        float4 av = a4[q], wv = w4[q];
        acc = __fmaf_rn(av.x, wv.x, acc);
        acc = __fmaf_rn(av.y, wv.y, acc);
        acc = __fmaf_rn(av.z, wv.z, acc);
        acc = __fmaf_rn(av.w, wv.w, acc);
    }
    return acc;
}

// ---------------------------------------------------------------- codebook norms
__global__ void norms_kernel(const float* __restrict__ cb) {
    int w    = (blockIdx.x * blockDim.x + threadIdx.x) >> 5;
    int lane = threadIdx.x & 31;
    if (w >= NL * NK) return;
    float s = warp_sumsq_x32(cb + (size_t)w * ND, lane);
    if (lane == 0) {
        g_norms[w] = s;
        atomicMax(&g_nsmax[w >> 10], __float_as_uint(s));
    }
}

// ---------------------------------------------------------------- pack codebook -> bf16 fragments
// slot within stage = ((kg*2+ngh)*4+pp)*32 + lane; stage = ntile*8+dchunk
__global__ void pack_kernel(const float* __restrict__ cb) {
    int gid  = blockIdx.x * blockDim.x + threadIdx.x;   // 0 .. NL*64*512-1
    int lane = gid & 31;
    int s16  = (gid >> 5) & 15;
    int pp   = s16 & 3, ng = (s16 >> 2) & 1, kg = s16 >> 3;
    int st   = (gid >> 9) & 63;
    int l    = gid >> 15;
    int code = (st >> 3) * TILEN + ng * 64 + pp * 16 + (lane >> 2);
    int d    = (st & 7) * 32 + kg * 16 + (lane & 3) * 2;
    const float* w = cb + ((size_t)l * NK + code) * ND + d;
    uint4 v;
    v.x = bf2(w[0], w[1]);
    v.y = bf2(w[8], w[9]);
    v.z = bf2(w[8 * ND], w[8 * ND + 1]);
    v.w = bf2(w[8 * ND + 8], w[8 * ND + 9]);
    g_wpack[gid] = v;
}

// ---------------------------------------------------------------- x (B,D,T) -> res (N,D)
__global__ void tin_kernel(const float* __restrict__ x) {
    __shared__ float tile[32][33];
    int b  = blockIdx.z;
    int d0 = blockIdx.y * 32, t0 = blockIdx.x * 32;
    int tx = threadIdx.x, ty = threadIdx.y;
    #pragma unroll
    for (int i = 0; i < 32; i += 8)
        tile[ty + i][tx] = x[((size_t)b * ND + d0 + ty + i) * NT + t0 + tx];
    __syncthreads();
    #pragma unroll
    for (int i = 0; i < 32; i += 8)
        g_res[((size_t)(b * NT + t0 + ty + i)) * ND + d0 + tx] = tile[tx][ty + i];
}

// ---------------------------------------------------------------- out = x - res
__global__ void tout_kernel(const float* __restrict__ x, float* __restrict__ out) {
    __shared__ float tile[32][33];
    int b  = blockIdx.z;
    int d0 = blockIdx.y * 32, t0 = blockIdx.x * 32;
    int tx = threadIdx.x, ty = threadIdx.y;
    #pragma unroll
    for (int i = 0; i < 32; i += 8)
        tile[ty + i][tx] = g_res[((size_t)(b * NT + t0 + ty + i)) * ND + d0 + tx];
    __syncthreads();
    size_t base = (size_t)b * ND * NT;
    #pragma unroll
    for (int i = 0; i < 32; i += 8) {
        size_t o = base + (size_t)(d0 + ty + i) * NT + t0 + tx;
        out[o] = __fsub_rn(x[o], tile[tx][ty + i]);
    }
}

// ---------------------------------------------------------------- one RVQ layer
__global__ void __launch_bounds__(NTHREADS, 2) vq_layer_kernel(
    const float* __restrict__ codebooks,
    float* __restrict__ idx_out,
    int l, int write_idx)
{
    extern __shared__ char smem[];
    uint4*    Atf4   = (uint4*)(smem + ATF_OFF);
    float*    Ns     = (float*)(smem + NS_OFF);
    float*    An     = (float*)(smem + AN_OFF);
    uint32_t* runmin = (uint32_t*)(smem + RM_OFF);
    int*      cnt    = (int*)(smem + CNT_OFF);
    int*      RowIdx = (int*)(smem + RI_OFF);
    uint32_t* cand   = (uint32_t*)(smem + CD_OFF);
    float*    pbv    = (float*)(smem + PBV_OFF);
    int*      pbi    = (int*)(smem + PBI_OFF);

    const float* W  = codebooks + (size_t)l * NK * ND;
    const int row0  = blockIdx.x * TM;
    const float* gA = g_res + (size_t)row0 * ND;
    const int tid   = threadIdx.x;
    const int lane  = tid & 31;
    const int warp  = tid >> 5;
    const int mg    = warp & 1;        // M-group (64 rows)
    const int ng    = warp >> 1;       // N-group (32 cols within ntile)
    const int lr    = lane >> 2, lc = lane & 3;
    const float nsM = __uint_as_float(g_nsmax[l]);

    for (int i = tid; i < NK; i += NTHREADS) Ns[i] = g_norms[l * NK + i];
    if (tid < TM) { cnt[tid] = 0; runmin[tid] = 0x7F7FFFFFu; }

    // ---- |r|^2 per row, XLA reduce order ----
    #pragma unroll
    for (int rr = 0; rr < TM / 8; rr++) {
        int r = rr * 8 + warp;
        float s = warp_sumsq_x32(&gA[(size_t)r * ND], lane);
        if (lane == 0) An[r] = s;
    }

    // ---- pack A as bf16 m16n8k16 fragments (once per layer) ----
    #pragma unroll
    for (int i = 0; i < 4096 / NTHREADS; i++) {
        int s   = tid + i * NTHREADS;
        int lb  = s & 31, kq = (s >> 5) & 15, mt = (s >> 9) & 1, mgi = s >> 10;
        int r   = mgi * 32 + mt * 16 + (lb >> 2);
        int k0  = kq * 16 + (lb & 3) * 2;
        float2 x0 = *(const float2*)(gA + (size_t)r * ND + k0);
        float2 x1 = *(const float2*)(gA + (size_t)(r + 8) * ND + k0);
        float2 x2 = *(const float2*)(gA + (size_t)r * ND + k0 + 8);
        float2 x3 = *(const float2*)(gA + (size_t)(r + 8) * ND + k0 + 8);
        Atf4[s] = make_uint4(bf2(x0.x, x0.y), bf2(x1.x, x1.y),
                             bf2(x2.x, x2.y), bf2(x3.x, x3.y));
    }
    __syncthreads();     // A buffer ready; NO barriers in mainloop after this

    // ---- per-warp B fragment slot addresses in g_wpack ----
    const uint4* wp = (const uint4*)g_wpack + (size_t)l * NSTG * 512;
    const int ngh = ng >> 1, ngl = ng & 1;
    int sb[4];
    #pragma unroll
    for (int kg = 0; kg < 2; kg++)
        #pragma unroll
        for (int p = 0; p < 2; p++)
            sb[kg * 2 + p] = ((kg * 2 + ngh) * 4 + ngl * 2 + p) * 32 + lane;

    const ull NEG2 = pack2(-2.f, -2.f);

    uint4 BA[4], BB[4];
    #pragma unroll
    for (int q = 0; q < 4; q++) BA[q] = wp[sb[q]];   // stage 0

    float accf[4][4][4];
    for (int t2 = 0; t2 < NSTG; t2 += 2) {
        if ((t2 & 7) == 0) {
            #pragma unroll
            for (int a = 0; a < 4; a++)
                #pragma unroll
                for (int b = 0; b < 4; b++)
                    #pragma unroll
                    for (int c = 0; c < 4; c++) accf[a][b][c] = 0.f;
        }
        // prefetch odd stage into BB, compute even stage from BA
        {
            const uint4* wn = wp + (size_t)(t2 + 1) * 512;
            #pragma unroll
            for (int q = 0; q < 4; q++) BB[q] = wn[sb[q]];
        }
        #pragma unroll
        for (int kg = 0; kg < 2; kg++) {
            const int kq = (t2 & 7) * 2 + kg;
            uint4 Af[4];
            #pragma unroll
            for (int mt = 0; mt < 4; mt++)
                Af[mt] = Atf4[((mg * 4 + mt) * 16 + kq) * 32 + lane];
            #pragma unroll
            for (int mt = 0; mt < 4; mt++) {
                uint32_t a[4] = {Af[mt].x, Af[mt].y, Af[mt].z, Af[mt].w};
                #pragma unroll
                for (int ns = 0; ns < 4; ns++) {
                    uint4 B = BA[kg * 2 + (ns >> 1)];
                    mma_bf16(accf[mt][ns], a, (ns & 1) ? B.z : B.x,
                                              (ns & 1) ? B.w : B.y);
                }
            }
        }
        // prefetch next even stage into BA, compute odd stage from BB
        {
            const uint4* wn = wp + (size_t)((t2 + 2 < NSTG) ? t2 + 2 : t2) * 512;
            #pragma unroll
            for (int q = 0; q < 4; q++) BA[q] = wn[sb[q]];
        }
        #pragma unroll
        for (int kg = 0; kg < 2; kg++) {
            const int kq = ((t2 + 1) & 7) * 2 + kg;
            uint4 Af[4];
            #pragma unroll
            for (int mt = 0; mt < 4; mt++)
                Af[mt] = Atf4[((mg * 4 + mt) * 16 + kq) * 32 + lane];
            #pragma unroll
            for (int mt = 0; mt < 4; mt++) {
                uint32_t a[4] = {Af[mt].x, Af[mt].y, Af[mt].z, Af[mt].w};
                #pragma unroll
                for (int ns = 0; ns < 4; ns++) {
                    uint4 B = BB[kg * 2 + (ns >> 1)];
                    mma_bf16(accf[mt][ns], a, (ns & 1) ? B.z : B.x,
                                              (ns & 1) ? B.w : B.y);
                }
            }
        }

        // ---- per-ntile epilogue (packed f32x2, single pass) ----
        if ((t2 & 7) == 6) {
            const int ntile = t2 >> 3;
            ull Ns2[4];
            #pragma unroll
            for (int ns = 0; ns < 4; ns++)
                Ns2[ns] = *(const ull*)&Ns[ntile * TILEN + ng * 32 + (ns >> 1) * 16
                                           + (ns & 1) * 8 + 2 * lc];
            #pragma unroll
            for (int mt = 0; mt < 4; mt++) {
                #pragma unroll
                for (int h = 0; h < 2; h++) {
                    int row = mg * 64 + mt * 16 + lr + 8 * h;
                    float A  = An[row];
                    float ee = 0.0159f * sqrtf(A * nsM) + 0.25f;
                    ull  A2  = pack2(A, A);
                    float dl[8]; float m = 3.4e38f;
                    #pragma unroll
                    for (int ns = 0; ns < 4; ns++) {
                        // dv = rn(rn(A - 2*acc) + Ns): fma(-2,acc,A) exact-equal
                        // to sub(A, mul(2,acc)) since 2*acc is exact.
                        ull acc2 = pack2(accf[mt][ns][2 * h], accf[mt][ns][2 * h + 1]);
                        float2 e = unpack2(fadd2(ffma2(acc2, NEG2, A2), Ns2[ns]));
                        dl[2 * ns] = e.x; dl[2 * ns + 1] = e.y;
                        m = fminf(m, fminf(e.x, e.y));
                    }
                    float m2 = fminf(m, __shfl_xor_sync(0xffffffffu, m, 1));
                    m2 = fminf(m2, __shfl_xor_sync(0xffffffffu, m2, 2));
                    float rm  = __uint_as_float(runmin[row]);    // racy = conservative
                    float thr = fminf(m2, rm) + ee;
                    #pragma unroll
                    for (int e8 = 0; e8 < 8; e8++) {
                        if (dl[e8] <= thr) {
                            int col = ntile * TILEN + ng * 32 + ((e8 >> 2) & 1) * 16
                                    + ((e8 >> 1) & 1) * 8 + 2 * lc + (e8 & 1);
                            int slot = atomicAdd(&cnt[row], 1);
                            if (slot < CAP)
                                cand[row * CAP + slot] =
                                    (__float_as_uint(fmaxf(dl[e8], 0.f)) & 0xFFFFFC00u)
                                    | (uint32_t)col;
                        }
                    }
                    if (lc == 0)
                        atomicMin(runmin + row, __float_as_uint(fmaxf(m2, 0.f)));
                }
            }
        }
    }
    __syncthreads();

    // ---- exact rescore: float4 loads + ILP-2 candidate pairs ----
    // Chain per candidate is the validated sequential ascending-d fmaf chain
    // (float4 load order == scalar order -> bit-identical). Pairing shares the
    // ar row load; (val,idx) min with index tie-break is order-independent.
    {
        int row = tid & (TM - 1), sl = tid >> 7;
        float A = An[row];
        float thrF = __uint_as_float(runmin[row]) + (0.0159f * sqrtf(A * nsM) + 0.25f);
        int n = cnt[row];
        float bv = 3.4e38f; int bi = 1 << 30;
        const float4* a4 = (const float4*)(gA + (size_t)row * ND);
        if (n <= CAP) {
            int mycols[CAP / 2]; int mc = 0;
            for (int s = sl; s < n; s += 2) {
                uint32_t u = cand[row * CAP + s];
                if (__uint_as_float(u & 0xFFFFFC00u) > thrF) continue;
                mycols[mc++] = (int)(u & 1023u);
            }
            int i = 0;
            for (; i + 1 < mc; i += 2) {
                int c0 = mycols[i], c1 = mycols[i + 1];
                const float4* w0 = (const float4*)(W + (size_t)c0 * ND);
                const float4* w1 = (const float4*)(W + (size_t)c1 * ND);
                float acc0 = 0.f, acc1 = 0.f;
                #pragma unroll 8
                for (int q = 0; q < ND / 4; q++) {
                    float4 av = a4[q], v0 = w0[q], v1 = w1[q];
                    acc0 = __fmaf_rn(av.x, v0.x, acc0);
                    acc1 = __fmaf_rn(av.x, v1.x, acc1);
                    acc0 = __fmaf_rn(av.y, v0.y, acc0);
                    acc1 = __fmaf_rn(av.y, v1.y, acc1);
                    acc0 = __fmaf_rn(av.z, v0.z, acc0);
                    acc1 = __fmaf_rn(av.z, v1.z, acc1);
                    acc0 = __fmaf_rn(av.w, v0.w, acc0);
                    acc1 = __fmaf_rn(av.w, v1.w, acc1);
                }
                float d0 = __fadd_rn(__fsub_rn(A, __fmul_rn(2.f, acc0)), Ns[c0]);
                float d1 = __fadd_rn(__fsub_rn(A, __fmul_rn(2.f, acc1)), Ns[c1]);
                if (d0 < bv || (d0 == bv && c0 < bi)) { bv = d0; bi = c0; }
                if (d1 < bv || (d1 == bv && c1 < bi)) { bv = d1; bi = c1; }
            }
            if (i < mc) {
                int c0 = mycols[i];
                float acc = dot_exact(a4, (const float4*)(W + (size_t)c0 * ND));
                float de = __fadd_rn(__fsub_rn(A, __fmul_rn(2.f, acc)), Ns[c0]);
                if (de < bv || (de == bv && c0 < bi)) { bv = de; bi = c0; }
            }
        } else {
            // candidate list overflowed: guaranteed-exact full scan (rare)
            for (int col = sl; col < NK; col += 2) {
                float acc = dot_exact(a4, (const float4*)(W + (size_t)col * ND));
                float de = __fadd_rn(__fsub_rn(A, __fmul_rn(2.f, acc)), Ns[col]);
                if (de < bv || (de == bv && col < bi)) { bv = de; bi = col; }
            }
        }
        pbv[row * 2 + sl] = bv;
        pbi[row * 2 + sl] = bi;
    }
    __syncthreads();
    if (tid < TM) {
        float bv = pbv[tid * 2]; int bi = pbi[tid * 2];
        float v = pbv[tid * 2 + 1]; int ii = pbi[tid * 2 + 1];
        if (v < bv || (v == bv && ii < bi)) { bv = v; bi = ii; }
        if (bi >= NK) bi = 0;               // unreachable by construction
        RowIdx[tid] = bi;
        if (write_idx) {
            int nn = row0 + tid;
            int b = nn >> 11;               // T = 2048
            int t = nn & (NT - 1);
            idx_out[(size_t)b * NL * NT + (size_t)l * NT + t] = (float)bi;
        }
    }
    __syncthreads();

    // ---- residual -= gathered code ----
    {
        float4*       gout = (float4*)(g_res + (size_t)row0 * ND);
        const float4* gin  = (const float4*)gA;
        #pragma unroll
        for (int it = 0; it < (TM * (ND / 4)) / NTHREADS; it++) {
            int e   = tid + it * NTHREADS;
            int row = e >> 6;
            int d4  = e & 63;
            float4 w4 = *(const float4*)(W + (size_t)RowIdx[row] * ND + 4 * d4);
            float4 a4v = gin[e];
            gout[e] = make_float4(__fsub_rn(a4v.x, w4.x), __fsub_rn(a4v.y, w4.y),
                                  __fsub_rn(a4v.z, w4.z), __fsub_rn(a4v.w, w4.w));
        }
    }
}

// ---------------------------------------------------------------- launch
extern "C" void kernel_launch(void* const* d_in, const int* in_sizes, int n_in,
                              void* d_out, int out_size) {
    const float* x  = (const float*)d_in[0];
    const float* cb = (const float*)d_in[1];
    if (n_in >= 2 && in_sizes[0] == NL * NK * ND && in_sizes[1] == NB * ND * NT) {
        const float* t = x; x = cb; cb = t;
    }
    float* out = (float*)d_out;
    int write_idx = (out_size >= NOUT + NIDX) ? 1 : 0;

    cudaFuncSetAttribute(vq_layer_kernel,
                         cudaFuncAttributeMaxDynamicSharedMemorySize, SMEM_BYTES);

    norms_kernel<<<(NL * NK * 32 + 255) / 256, 256>>>(cb);
    pack_kernel<<<NL * NSTG * 512 / 256, 256>>>(cb);

    dim3 tb(32, 8);
    tin_kernel<<<dim3(NT / 32, ND / 32, NB), tb>>>(x);

    for (int l = 0; l < NL; l++)
        vq_layer_kernel<<<NVEC / TM, NTHREADS, SMEM_BYTES>>>(cb, out + NOUT, l, write_idx);

    tout_kernel<<<dim3(NT / 32, ND / 32, NB), tb>>>(x, out);
}